// round 5
// baseline (speedup 1.0000x reference)
#include <cuda_runtime.h>

#define NN 65536
#define EE 524288
#define BBG 256
#define FEAT 64
#define EMB 128
#define NHD 4
#define OUTD 32
#define NEG_INF __int_as_float(0xff800000)

// conv0F tiling
#define CN 64            // nodes per block
#define APITCH 68        // input tile pitch ([k][n]) - 16B aligned rows, conflict-shifted
#define WPITCH 132       // weight tile pitch ([k][j])

// ---------------- scratch (static device globals; no allocation) ----------------
__device__ float g_aggf[NN * FEAT];
__device__ float g_buf[NN * EMB];
__device__ float g_cur[NN * EMB];
__device__ float g_sm[NHD * NN];
__device__ unsigned char g_mask[NN];
__device__ float g_part[1024 * EMB];
__device__ float g_part2[1024 * EMB];
__device__ float g_meanvar[2 * EMB];
__device__ int g_klist[BBG * 256];
__device__ int g_kcnt[BBG];
__device__ int g_deg[NN];
__device__ int g_rp[NN + 1];
__device__ int g_cursor[NN];
__device__ int g_csrc[EE];

__device__ __forceinline__ float lrelu(float v) { return v > 0.f ? v : 0.01f * v; }

typedef unsigned long long u64;
__device__ __forceinline__ u64 ffma2(u64 a, u64 b, u64 c) {
    u64 d;
    asm("fma.rn.f32x2 %0, %1, %2, %3;" : "=l"(d) : "l"(a), "l"(b), "l"(c));
    return d;
}
__device__ __forceinline__ u64 pack2(float x) {
    u64 r;
    asm("mov.b64 %0, {%1, %1};" : "=l"(r) : "f"(x));
    return r;
}
__device__ __forceinline__ float2 unpack2(u64 v) {
    float2 r;
    asm("mov.b64 {%0, %1}, %2;" : "=f"(r.x), "=f"(r.y) : "l"(v));
    return r;
}

// ---------------- CSR build (by dst); g_deg zeroed by cudaMemsetAsync ----------------
__global__ void k_hist(const int* __restrict__ dst) {
    int e = blockIdx.x * blockDim.x + threadIdx.x;
    if (e < EE) atomicAdd(&g_deg[dst[e]], 1);
}

// single-block full scan: 1024 threads x 64 elements
__global__ void k_scanF() {
    int t = threadIdx.x;
    int s = 0;
#pragma unroll 8
    for (int i = 0; i < 64; i++) s += g_deg[t * 64 + i];
    __shared__ int a[1024];
    a[t] = s;
    __syncthreads();
    for (int off = 1; off < 1024; off <<= 1) {
        int v = (t >= off) ? a[t - off] : 0;
        __syncthreads();
        a[t] += v;
        __syncthreads();
    }
    int run = a[t] - s;   // exclusive prefix of this chunk
#pragma unroll 8
    for (int i = 0; i < 64; i++) {
        int d = g_deg[t * 64 + i];
        g_rp[t * 64 + i] = run;
        g_cursor[t * 64 + i] = run;
        run += d;
    }
    if (t == 1023) g_rp[NN] = EE;
}

__global__ void k_scatter(const int* __restrict__ src, const int* __restrict__ dst) {
    int e = blockIdx.x * blockDim.x + threadIdx.x;
    if (e < EE) {
        int p = atomicAdd(&g_cursor[dst[e]], 1);
        g_csrc[p] = src[e];
    }
}

// ---------------- conv0 max aggregation (warp per node) ----------------
__global__ void k_agg0(const float* __restrict__ x) {
    int wi = (blockIdx.x * blockDim.x + threadIdx.x) >> 5;
    if (wi >= NN) return;
    int lane = threadIdx.x & 31;
    int beg = g_rp[wi], end = g_rp[wi + 1];
    float m0 = -3.4e38f, m1 = -3.4e38f;
    for (int e = beg; e < end; e++) {
        int s = g_csrc[e];
        m0 = fmaxf(m0, x[s * FEAT + lane]);
        m1 = fmaxf(m1, x[s * FEAT + 32 + lane]);
    }
    if (beg == end) { m0 = 0.f; m1 = 0.f; }
    g_aggf[wi * FEAT + lane] = m0;
    g_aggf[wi * FEAT + 32 + lane] = m1;
}

// ---------------- conv0 GEMM (f32x2 packed) + fused BN partials ----------------
// 64 nodes/block, 256 threads. thread: ncol = tx&7 (8 nodes), orow = tx>>3 (4 outs)
// dynamic smem: sA[64][APITCH] | sX[64][APITCH] | sW[2][64][WPITCH]
__global__ void __launch_bounds__(256) k_conv0F(const float* __restrict__ x,
                                                const float* __restrict__ wrel,
                                                const float* __restrict__ wroot,
                                                const float* __restrict__ b0) {
    extern __shared__ float sm[];
    float* sA = sm;                        // 64*APITCH
    float* sX = sm + 64 * APITCH;          // 64*APITCH
    float* sW = sm + 2 * 64 * APITCH;      // 2*64*WPITCH
    int tx = threadIdx.x;
    int nbase = blockIdx.x * CN;

    // load input tiles: [k][n] layout
#pragma unroll
    for (int r = 0; r < 16; r++) {
        int idx = r * 256 + tx;            // 4096 elems
        int n = idx >> 6, k = idx & 63;
        sA[k * APITCH + n] = g_aggf[(nbase + n) * FEAT + k];
        sX[k * APITCH + n] = x[(nbase + n) * FEAT + k];
    }
    // load weights: [m][k][j]
#pragma unroll
    for (int r = 0; r < 32; r++) {
        int lin = r * 256 + tx;            // 8192 per matrix
        int j = lin >> 6, k = lin & 63;
        sW[k * WPITCH + j] = wrel[j * FEAT + k];
        sW[64 * WPITCH + k * WPITCH + j] = wroot[j * FEAT + k];
    }
    __syncthreads();

    int ncol = tx & 7;                     // node group: n0 = ncol*8
    int orow = tx >> 3;                    // out group: j0 = orow*4
    int n0 = ncol * 8;
    int j0 = orow * 4;

    u64 acc[4][4];
#pragma unroll
    for (int p = 0; p < 4; p++)
#pragma unroll
        for (int q = 0; q < 4; q++) acc[p][q] = 0ull;

#pragma unroll
    for (int m = 0; m < 2; m++) {
        const float* sIn = m ? sX : sA;
        const float* sWm = sW + m * 64 * WPITCH;
#pragma unroll 8
        for (int k = 0; k < 64; k++) {
            ulonglong2 va = *(const ulonglong2*)&sIn[k * APITCH + n0];      // nodes n0..n0+3
            ulonglong2 vb = *(const ulonglong2*)&sIn[k * APITCH + n0 + 4];  // nodes n0+4..n0+7
            float4 wv = *(const float4*)&sWm[k * WPITCH + j0];
            u64 w0 = pack2(wv.x), w1 = pack2(wv.y), w2 = pack2(wv.z), w3 = pack2(wv.w);
            acc[0][0] = ffma2(va.x, w0, acc[0][0]);
            acc[0][1] = ffma2(va.x, w1, acc[0][1]);
            acc[0][2] = ffma2(va.x, w2, acc[0][2]);
            acc[0][3] = ffma2(va.x, w3, acc[0][3]);
            acc[1][0] = ffma2(va.y, w0, acc[1][0]);
            acc[1][1] = ffma2(va.y, w1, acc[1][1]);
            acc[1][2] = ffma2(va.y, w2, acc[1][2]);
            acc[1][3] = ffma2(va.y, w3, acc[1][3]);
            acc[2][0] = ffma2(vb.x, w0, acc[2][0]);
            acc[2][1] = ffma2(vb.x, w1, acc[2][1]);
            acc[2][2] = ffma2(vb.x, w2, acc[2][2]);
            acc[2][3] = ffma2(vb.x, w3, acc[2][3]);
            acc[3][0] = ffma2(vb.y, w0, acc[3][0]);
            acc[3][1] = ffma2(vb.y, w1, acc[3][1]);
            acc[3][2] = ffma2(vb.y, w2, acc[3][2]);
            acc[3][3] = ffma2(vb.y, w3, acc[3][3]);
        }
    }
    __syncthreads();   // all GEMM reads done; reuse sA region for BN partials

    float4 bb = *(const float4*)&b0[j0];
    float s[4] = {0, 0, 0, 0}, ss[4] = {0, 0, 0, 0};
#pragma unroll
    for (int p = 0; p < 8; p++) {
        int p2 = p >> 1, half = p & 1;
        float2 v0 = unpack2(acc[p2][0]);
        float2 v1 = unpack2(acc[p2][1]);
        float2 v2 = unpack2(acc[p2][2]);
        float2 v3 = unpack2(acc[p2][3]);
        float a0 = half ? v0.y : v0.x;
        float a1 = half ? v1.y : v1.x;
        float a2 = half ? v2.y : v2.x;
        float a3 = half ? v3.y : v3.x;
        a0 = lrelu(a0 + bb.x);
        a1 = lrelu(a1 + bb.y);
        a2 = lrelu(a2 + bb.z);
        a3 = lrelu(a3 + bb.w);
        int node = nbase + n0 + p;
        float4 o = {a0, a1, a2, a3};
        *(float4*)&g_buf[node * EMB + j0] = o;
        s[0] += a0; ss[0] += a0 * a0;
        s[1] += a1; ss[1] += a1 * a1;
        s[2] += a2; ss[2] += a2 * a2;
        s[3] += a3; ss[3] += a3 * a3;
    }
    float2* pr = (float2*)sA;   // [feature 0..127][ncol 0..7]
#pragma unroll
    for (int q = 0; q < 4; q++)
        pr[(j0 + q) * 8 + ncol] = make_float2(s[q], ss[q]);
    __syncthreads();
    if (tx < 128) {
        float a = 0.f, a2 = 0.f;
#pragma unroll
        for (int w = 0; w < 8; w++) {
            float2 v = pr[tx * 8 + w];
            a += v.x; a2 += v.y;
        }
        g_part[blockIdx.x * EMB + tx] = a;
        g_part2[blockIdx.x * EMB + tx] = a2;
    }
}

// ---------------- reduce partials -> mean, inv-std ----------------
__global__ void k_statsR(int P) {
    int f = blockIdx.x, t = threadIdx.x;
    float s = 0.f, ss = 0.f;
    for (int p = t; p < P; p += 256) {
        s += g_part[p * EMB + f];
        ss += g_part2[p * EMB + f];
    }
    __shared__ float r1[256], r2[256];
    r1[t] = s; r2[t] = ss;
    __syncthreads();
    for (int o = 128; o > 0; o >>= 1) {
        if (t < o) { r1[t] += r1[t + o]; r2[t] += r2[t + o]; }
        __syncthreads();
    }
    if (t == 0) {
        float mean = r1[0] * (1.f / NN);
        float var = r2[0] * (1.f / NN) - mean * mean;
        g_meanvar[f] = mean;
        g_meanvar[EMB + f] = 1.f / sqrtf(var + 1e-5f);
    }
}

// ---------------- fused: BN-apply/update + pool scores + softmax + keep + compact ----------------
__global__ void k_A(int mode, const float* __restrict__ gam, const float* __restrict__ bet,
                    const float* __restrict__ w4, float min_score) {
    int g = blockIdx.x, t = threadIdx.x;
    int w = t >> 5, lane = t & 31;
    __shared__ float sG[128], sBt[128], sMu[128], sRs[128];
    __shared__ float sW[4 * 128];
    __shared__ float sc[4][256];
    __shared__ float red[256];
    __shared__ int iarr[256];
    if (t < 128) {
        sG[t] = gam[t]; sBt[t] = bet[t];
        sMu[t] = g_meanvar[t]; sRs[t] = g_meanvar[EMB + t];
    }
    sW[t] = w4[t];
    sW[256 + t] = w4[256 + t];
    __syncthreads();

    int f0 = lane * 4;
    float4 gg = *(float4*)&sG[f0], bb = *(float4*)&sBt[f0];
    float4 mm = *(float4*)&sMu[f0], rr = *(float4*)&sRs[f0];
    float4 w0v = *(float4*)&sW[0 * 128 + f0];
    float4 w1v = *(float4*)&sW[1 * 128 + f0];
    float4 w2v = *(float4*)&sW[2 * 128 + f0];
    float4 w3v = *(float4*)&sW[3 * 128 + f0];

    for (int i = 0; i < 32; i++) {
        int gi = g * 256 + w * 32 + i;
        float4 v;
        if (mode == 0) {
            float4 b = *(const float4*)&g_buf[gi * EMB + f0];
            v.x = gg.x * (b.x - mm.x) * rr.x + bb.x;
            v.y = gg.y * (b.y - mm.y) * rr.y + bb.y;
            v.z = gg.z * (b.z - mm.z) * rr.z + bb.z;
            v.w = gg.w * (b.w - mm.w) * rr.w + bb.w;
        } else {
            float4 c = *(const float4*)&g_cur[gi * EMB + f0];
            unsigned mb = g_mask[gi];
            float4 b = {0.f, 0.f, 0.f, 0.f};
            if (mb) b = *(const float4*)&g_buf[gi * EMB + f0];
            float n0 = gg.x * (b.x - mm.x) * rr.x + bb.x;
            float n1 = gg.y * (b.y - mm.y) * rr.y + bb.y;
            float n2 = gg.z * (b.z - mm.z) * rr.z + bb.z;
            float n3 = gg.w * (b.w - mm.w) * rr.w + bb.w;
            v.x = 0.5f * c.x + 0.25f * n0;
            v.y = 0.5f * c.y + 0.25f * n1;
            v.z = 0.5f * c.z + 0.25f * n2;
            v.w = 0.5f * c.w + 0.25f * n3;
        }
        *(float4*)&g_cur[gi * EMB + f0] = v;
        float p0 = v.x * w0v.x + v.y * w0v.y + v.z * w0v.z + v.w * w0v.w;
        float p1 = v.x * w1v.x + v.y * w1v.y + v.z * w1v.z + v.w * w1v.w;
        float p2 = v.x * w2v.x + v.y * w2v.y + v.z * w2v.z + v.w * w2v.w;
        float p3 = v.x * w3v.x + v.y * w3v.y + v.z * w3v.z + v.w * w3v.w;
#pragma unroll
        for (int o = 16; o; o >>= 1) {
            p0 += __shfl_xor_sync(0xffffffffu, p0, o);
            p1 += __shfl_xor_sync(0xffffffffu, p1, o);
            p2 += __shfl_xor_sync(0xffffffffu, p2, o);
            p3 += __shfl_xor_sync(0xffffffffu, p3, o);
        }
        if (lane == 0) {
            int n = w * 32 + i;
            sc[0][n] = p0; sc[1][n] = p1; sc[2][n] = p2; sc[3][n] = p3;
        }
    }
    __syncthreads();

    unsigned mb = 0;
    for (int h = 0; h < NHD; h++) {
        float vv = sc[h][t];
        red[t] = vv; __syncthreads();
        for (int o = 128; o > 0; o >>= 1) {
            if (t < o) red[t] = fmaxf(red[t], red[t + o]);
            __syncthreads();
        }
        float m = red[0]; __syncthreads();
        float e = expf(vv - m);
        red[t] = e; __syncthreads();
        for (int o = 128; o > 0; o >>= 1) {
            if (t < o) red[t] += red[t + o];
            __syncthreads();
        }
        float s = red[0]; __syncthreads();
        float sm = e / (s + 1e-16f);
        float smax = 1.0f / (s + 1e-16f);
        float thr = fminf(smax - 1e-7f, min_score);
        if (sm > thr) mb |= (1u << h);
        g_sm[h * NN + g * 256 + t] = sm;
    }
    g_mask[g * 256 + t] = (unsigned char)mb;

    int flag = mb ? 1 : 0;
    iarr[t] = flag; __syncthreads();
    for (int off = 1; off < 256; off <<= 1) {
        int xv = (t >= off) ? iarr[t - off] : 0;
        __syncthreads(); iarr[t] += xv; __syncthreads();
    }
    if (flag) g_klist[g * 256 + iarr[t] - 1] = t | ((int)mb << 8);
    if (t == 255) g_kcnt[g] = iarr[255];
}

// ---------------- block head conv on kept nodes + fused BN partials ----------------
__global__ void k_head(const float* __restrict__ wrel, const float* __restrict__ wroot,
                       const float* __restrict__ bias) {
    int g = blockIdx.x, t = threadIdx.x;
    int cnt = g_kcnt[g];
    int h = t >> 5, j = t & 31;
    __shared__ float sCur[128];
    __shared__ float sAgg[NHD][128];
    float s_acc = 0.f, ss_acc = 0.f;
    for (int kk = 0; kk < cnt; kk++) {
        int pk = g_klist[g * 256 + kk];
        int i = g * 256 + (pk & 255);
        unsigned mb = (pk >> 8) & 15;
        sCur[t] = g_cur[i * EMB + t];
        int beg = g_rp[i], end = g_rp[i + 1];
#pragma unroll
        for (int hh = 0; hh < NHD; hh++) {
            if (!((mb >> hh) & 1)) continue;
            float m = -3.4e38f;
            bool any = false;
            for (int e = beg; e < end; e++) {
                int sidx = g_csrc[e];
                if ((g_mask[sidx] >> hh) & 1) {
                    m = fmaxf(m, g_cur[sidx * EMB + t] * g_sm[hh * NN + sidx]);
                    any = true;
                }
            }
            sAgg[hh][t] = any ? m : 0.f;
        }
        __syncthreads();
        float v = 0.f;
        if ((mb >> h) & 1) {
            float smv = g_sm[h * NN + i];
            float accv = bias[h * OUTD + j];
            const float* wr = &wrel[(h * OUTD + j) * EMB];
            const float* wo = &wroot[(h * OUTD + j) * EMB];
#pragma unroll 16
            for (int k = 0; k < EMB; k++)
                accv += wr[k] * sAgg[h][k] + wo[k] * (sCur[k] * smv);
            v = lrelu(accv);
        }
        g_buf[i * EMB + t] = v;
        s_acc += v; ss_acc += v * v;
        __syncthreads();
    }
    g_part[g * EMB + t] = s_acc;
    g_part2[g * EMB + t] = ss_acc;
}

// ---------------- fused classifier ----------------
__global__ void k_cls(const float* __restrict__ gW1, const float* __restrict__ gb1,
                      const float* __restrict__ gW2, const float* __restrict__ gb2,
                      const float* __restrict__ fW1, const float* __restrict__ fb1,
                      const float* __restrict__ fW2, const float* __restrict__ fb2,
                      float* __restrict__ out) {
    int g = blockIdx.x, t = threadIdx.x;
    __shared__ float gate_s[NHD][256];
    __shared__ float red[128];
    __shared__ float sCur[128];
    __shared__ float sPool[128];
    __shared__ float sLog[NHD];
    for (int idx = t; idx < NHD * 256; idx += 128)
        ((float*)gate_s)[idx] = NEG_INF;
    int cnt = g_kcnt[g];
    __syncthreads();

    for (int kk = 0; kk < cnt; kk++) {
        int pk = g_klist[g * 256 + kk];
        int n = pk & 255;
        unsigned mb = (pk >> 8) & 15;
        int i = g * 256 + n;
        sCur[t] = g_cur[i * EMB + t];
        __syncthreads();
        for (int c = 0; c < NHD; c++) {
            if (!((mb >> c) & 1)) continue;
            float smv = g_sm[c * NN + i];
            float accv = gb1[c * EMB + t];
            const float* wp = &gW1[(c * EMB + t) * EMB];
#pragma unroll 16
            for (int k = 0; k < EMB; k++) accv += wp[k] * (sCur[k] * smv);
            accv = lrelu(accv);
            red[t] = accv * gW2[c * EMB + t];
            __syncthreads();
            for (int o = 64; o > 0; o >>= 1) {
                if (t < o) red[t] += red[t + o];
                __syncthreads();
            }
            if (t == 0) gate_s[c][n] = red[0] + gb2[c];
            __syncthreads();
        }
        __syncthreads();
    }

    for (int c = 0; c < NHD; c++) {
        red[t] = fmaxf(gate_s[c][t], gate_s[c][t + 128]);
        __syncthreads();
        for (int o = 64; o > 0; o >>= 1) {
            if (t < o) red[t] = fmaxf(red[t], red[t + o]);
            __syncthreads();
        }
        float m = red[0]; __syncthreads();
        float e0 = expf(gate_s[c][t] - m);
        float e1 = expf(gate_s[c][t + 128] - m);
        red[t] = e0 + e1;
        __syncthreads();
        for (int o = 64; o > 0; o >>= 1) {
            if (t < o) red[t] += red[t + o];
            __syncthreads();
        }
        float s = red[0] + 1e-16f; __syncthreads();

        float pool = 0.f;
        for (int kk = 0; kk < cnt; kk++) {
            int pk = g_klist[g * 256 + kk];
            int n = pk & 255;
            unsigned mb = (pk >> 8) & 15;
            if (!((mb >> c) & 1)) continue;
            int i = g * 256 + n;
            float a = expf(gate_s[c][n] - m) / s;
            pool += a * g_sm[c * NN + i] * g_cur[i * EMB + t];
        }
        sPool[t] = pool;
        __syncthreads();
        float accv = fb1[c * EMB + t];
        const float* wp = &fW1[(c * EMB + t) * EMB];
#pragma unroll 16
        for (int k = 0; k < EMB; k++) accv += wp[k] * sPool[k];
        accv = lrelu(accv);
        red[t] = accv * fW2[c * EMB + t];
        __syncthreads();
        for (int o = 64; o > 0; o >>= 1) {
            if (t < o) red[t] += red[t + o];
            __syncthreads();
        }
        if (t == 0) sLog[c] = red[0] + fb2[c];
        __syncthreads();
    }

    if (t < NHD) {
        float m = fmaxf(fmaxf(sLog[0], sLog[1]), fmaxf(sLog[2], sLog[3]));
        float s = expf(sLog[0] - m) + expf(sLog[1] - m) + expf(sLog[2] - m) + expf(sLog[3] - m);
        out[g * NHD + t] = sLog[t] - m - logf(s);
    }
}

// ---------------- launch ----------------
extern "C" void kernel_launch(void* const* d_in, const int* in_sizes, int n_in,
                              void* d_out, int out_size) {
    const float* x       = (const float*)d_in[0];
    const int*   ei      = (const int*)d_in[1];
    const int*   src     = ei;
    const int*   dst     = ei + EE;
    const float* Wrel0   = (const float*)d_in[3];
    const float* Wroot0  = (const float*)d_in[4];
    const float* b0      = (const float*)d_in[5];
    const float* bn0g    = (const float*)d_in[6];
    const float* bn0b    = (const float*)d_in[7];
    const float* blk_pw  = (const float*)d_in[8];
    const float* blk_Wr  = (const float*)d_in[9];
    const float* blk_Wo  = (const float*)d_in[10];
    const float* blk_bb  = (const float*)d_in[11];
    const float* blk_bng = (const float*)d_in[12];
    const float* blk_bnb = (const float*)d_in[13];
    const float* cls_pw  = (const float*)d_in[14];
    const float* gW1     = (const float*)d_in[15];
    const float* gb1     = (const float*)d_in[16];
    const float* gW2     = (const float*)d_in[17];
    const float* gb2     = (const float*)d_in[18];
    const float* fW1     = (const float*)d_in[19];
    const float* fb1     = (const float*)d_in[20];
    const float* fW2     = (const float*)d_in[21];
    const float* fb2     = (const float*)d_in[22];
    float* out = (float*)d_out;

    const int CONV_SMEM = (2 * 64 * APITCH + 2 * 64 * WPITCH) * 4;  // 102400 B
    cudaFuncSetAttribute(k_conv0F, cudaFuncAttributeMaxDynamicSharedMemorySize, CONV_SMEM);

    void* degp = 0;
    cudaGetSymbolAddress(&degp, g_deg);

    // CSR by dst
    cudaMemsetAsync(degp, 0, NN * sizeof(int), 0);
    k_hist<<<EE / 256, 256>>>(dst);
    k_scanF<<<1, 1024>>>();
    k_scatter<<<EE / 256, 256>>>(src, dst);

    // conv0 (+ fused stats) -> statsR -> A0
    k_agg0<<<NN / 8, 256>>>(x);
    k_conv0F<<<NN / CN, 256, CONV_SMEM>>>(x, Wrel0, Wroot0, b0);
    k_statsR<<<EMB, 256>>>(NN / CN);
    k_A<<<BBG, 256>>>(0, bn0g, bn0b, blk_pw + 0 * NHD * EMB, 0.7f);

    // block 0
    k_head<<<BBG, 128>>>(blk_Wr, blk_Wo, blk_bb);
    k_statsR<<<EMB, 256>>>(BBG);
    k_A<<<BBG, 256>>>(1, blk_bng, blk_bnb, blk_pw + 1 * NHD * EMB, 0.7f);

    // block 1
    k_head<<<BBG, 128>>>(blk_Wr + NHD * OUTD * EMB, blk_Wo + NHD * OUTD * EMB, blk_bb + NHD * OUTD);
    k_statsR<<<EMB, 256>>>(BBG);
    k_A<<<BBG, 256>>>(1, blk_bng + EMB, blk_bnb + EMB, cls_pw, 0.8f);

    // classifier heads
    k_cls<<<BBG, 128>>>(gW1, gb1, gW2, gb2, fW1, fb1, fW2, fb2, out);
}

// round 7
// speedup vs baseline: 1.0101x; 1.0101x over previous
#include <cuda_runtime.h>

#define NN 65536
#define EE 524288
#define BBG 256
#define FEAT 64
#define EMB 128
#define NHD 4
#define OUTD 32
#define NEG_INF __int_as_float(0xff800000)

// ---------------- scratch (static device globals; no allocation) ----------------
__device__ float g_aggf[NN * FEAT];
__device__ float g_buf[NN * EMB];
__device__ float g_cur[NN * EMB];
__device__ float g_sm[NHD * NN];
__device__ unsigned char g_mask[NN];
__device__ float g_part[2048 * EMB];
__device__ float g_part2[2048 * EMB];
__device__ float g_meanvar[2 * EMB];
__device__ int g_klist[BBG * 256];
__device__ int g_kcnt[BBG];
__device__ int g_deg[NN];
__device__ int g_rp[NN + 1];
__device__ int g_cursor[NN];
__device__ int g_csrc[EE];

__device__ __forceinline__ float lrelu(float v) { return v > 0.f ? v : 0.01f * v; }

// ---------------- CSR build (by dst); g_deg zeroed by cudaMemsetAsync ----------------
__global__ void k_hist(const int* __restrict__ dst) {
    int e = blockIdx.x * blockDim.x + threadIdx.x;
    if (e < EE) atomicAdd(&g_deg[dst[e]], 1);
}

// single-block full scan: 1024 threads x 64 elements
__global__ void k_scanF() {
    int t = threadIdx.x;
    int s = 0;
#pragma unroll 8
    for (int i = 0; i < 64; i++) s += g_deg[t * 64 + i];
    __shared__ int a[1024];
    a[t] = s;
    __syncthreads();
    for (int off = 1; off < 1024; off <<= 1) {
        int v = (t >= off) ? a[t - off] : 0;
        __syncthreads();
        a[t] += v;
        __syncthreads();
    }
    int run = a[t] - s;
#pragma unroll 8
    for (int i = 0; i < 64; i++) {
        int d = g_deg[t * 64 + i];
        g_rp[t * 64 + i] = run;
        g_cursor[t * 64 + i] = run;
        run += d;
    }
    if (t == 1023) g_rp[NN] = EE;
}

__global__ void k_scatter(const int* __restrict__ src, const int* __restrict__ dst) {
    int e = blockIdx.x * blockDim.x + threadIdx.x;
    if (e < EE) {
        int p = atomicAdd(&g_cursor[dst[e]], 1);
        g_csrc[p] = src[e];
    }
}

// ---------------- conv0 max aggregation (warp per node) ----------------
__global__ void k_agg0(const float* __restrict__ x) {
    int wi = (blockIdx.x * blockDim.x + threadIdx.x) >> 5;
    if (wi >= NN) return;
    int lane = threadIdx.x & 31;
    int beg = g_rp[wi], end = g_rp[wi + 1];
    float m0 = -3.4e38f, m1 = -3.4e38f;
    for (int e = beg; e < end; e++) {
        int s = g_csrc[e];
        m0 = fmaxf(m0, x[s * FEAT + lane]);
        m1 = fmaxf(m1, x[s * FEAT + 32 + lane]);
    }
    if (beg == end) { m0 = 0.f; m1 = 0.f; }
    g_aggf[wi * FEAT + lane] = m0;
    g_aggf[wi * FEAT + 32 + lane] = m1;
}

// ---------------- conv0 GEMM + fused BN partial stats (R4-proven tile) ----------------
// 256 thr, 32 nodes/block, register tile 4 nodes x 4 outs
__global__ void k_conv0(const float* __restrict__ x, const float* __restrict__ wrel,
                        const float* __restrict__ wroot, const float* __restrict__ b0) {
    __shared__ float sW[64 * 132];
    __shared__ float sIn[64 * 36];
    int tx = threadIdx.x;
    int og = tx & 31;
    int ng = tx >> 5;
    int nbase = blockIdx.x * 32;

    float acc[4][4];
#pragma unroll
    for (int p = 0; p < 4; p++)
#pragma unroll
        for (int q = 0; q < 4; q++) acc[p][q] = 0.f;

    for (int c = 0; c < 2; c++) {
        const float* W = c ? wroot : wrel;
        const float* In = c ? x : g_aggf;
#pragma unroll
        for (int r = 0; r < 32; r++) {
            int lin = r * 256 + tx;
            int j = lin >> 6, k = lin & 63;
            sW[k * 132 + j] = W[j * 64 + k];
        }
#pragma unroll
        for (int r = 0; r < 8; r++) {
            int lin = r * 256 + tx;
            int n = lin >> 6, k = lin & 63;
            sIn[k * 36 + n] = In[(nbase + n) * 64 + k];
        }
        __syncthreads();
#pragma unroll 16
        for (int k = 0; k < 64; k++) {
            float4 wv = *(const float4*)&sW[k * 132 + og * 4];
            float4 iv = *(const float4*)&sIn[k * 36 + ng * 4];
            acc[0][0] += iv.x * wv.x; acc[0][1] += iv.x * wv.y; acc[0][2] += iv.x * wv.z; acc[0][3] += iv.x * wv.w;
            acc[1][0] += iv.y * wv.x; acc[1][1] += iv.y * wv.y; acc[1][2] += iv.y * wv.z; acc[1][3] += iv.y * wv.w;
            acc[2][0] += iv.z * wv.x; acc[2][1] += iv.z * wv.y; acc[2][2] += iv.z * wv.z; acc[2][3] += iv.z * wv.w;
            acc[3][0] += iv.w * wv.x; acc[3][1] += iv.w * wv.y; acc[3][2] += iv.w * wv.z; acc[3][3] += iv.w * wv.w;
        }
        __syncthreads();
    }
    int j0 = og * 4;
    float4 bb = *(const float4*)&b0[j0];
    float s[4] = {0, 0, 0, 0}, ss[4] = {0, 0, 0, 0};
#pragma unroll
    for (int p = 0; p < 4; p++) {
        int node = nbase + ng * 4 + p;
        float v0 = lrelu(acc[p][0] + bb.x);
        float v1 = lrelu(acc[p][1] + bb.y);
        float v2 = lrelu(acc[p][2] + bb.z);
        float v3 = lrelu(acc[p][3] + bb.w);
        float4 o = {v0, v1, v2, v3};
        *(float4*)&g_buf[node * EMB + j0] = o;
        s[0] += v0; ss[0] += v0 * v0;
        s[1] += v1; ss[1] += v1 * v1;
        s[2] += v2; ss[2] += v2 * v2;
        s[3] += v3; ss[3] += v3 * v3;
    }
    float2* pr = (float2*)sW;
#pragma unroll
    for (int q = 0; q < 4; q++)
        pr[(j0 + q) * 8 + ng] = make_float2(s[q], ss[q]);
    __syncthreads();
    if (tx < 128) {
        float a = 0.f, a2 = 0.f;
#pragma unroll
        for (int w = 0; w < 8; w++) {
            float2 v = pr[tx * 8 + w];
            a += v.x; a2 += v.y;
        }
        g_part[blockIdx.x * EMB + tx] = a;
        g_part2[blockIdx.x * EMB + tx] = a2;
    }
}

// ---------------- reduce partials -> mean, inv-std ----------------
__global__ void k_statsR(int P) {
    int f = blockIdx.x, t = threadIdx.x;
    float s = 0.f, ss = 0.f;
    for (int p = t; p < P; p += 256) {
        s += g_part[p * EMB + f];
        ss += g_part2[p * EMB + f];
    }
    __shared__ float r1[256], r2[256];
    r1[t] = s; r2[t] = ss;
    __syncthreads();
    for (int o = 128; o > 0; o >>= 1) {
        if (t < o) { r1[t] += r1[t + o]; r2[t] += r2[t + o]; }
        __syncthreads();
    }
    if (t == 0) {
        float mean = r1[0] * (1.f / NN);
        float var = r2[0] * (1.f / NN) - mean * mean;
        g_meanvar[f] = mean;
        g_meanvar[EMB + f] = 1.f / sqrtf(var + 1e-5f);
    }
}

// ---------------- fused: BN-apply/update + pool scores + softmax + keep + compact ----------------
__global__ void k_A(int mode, const float* __restrict__ gam, const float* __restrict__ bet,
                    const float* __restrict__ w4, float min_score) {
    int g = blockIdx.x, t = threadIdx.x;
    int w = t >> 5, lane = t & 31;
    __shared__ float sG[128], sBt[128], sMu[128], sRs[128];
    __shared__ float sW[4 * 128];
    __shared__ float sc[4][256];
    __shared__ float red[256];
    __shared__ int iarr[256];
    if (t < 128) {
        sG[t] = gam[t]; sBt[t] = bet[t];
        sMu[t] = g_meanvar[t]; sRs[t] = g_meanvar[EMB + t];
    }
    sW[t] = w4[t];
    sW[256 + t] = w4[256 + t];
    __syncthreads();

    int f0 = lane * 4;
    float4 gg = *(float4*)&sG[f0], bb = *(float4*)&sBt[f0];
    float4 mm = *(float4*)&sMu[f0], rr = *(float4*)&sRs[f0];
    float4 w0v = *(float4*)&sW[0 * 128 + f0];
    float4 w1v = *(float4*)&sW[1 * 128 + f0];
    float4 w2v = *(float4*)&sW[2 * 128 + f0];
    float4 w3v = *(float4*)&sW[3 * 128 + f0];

    for (int i = 0; i < 32; i++) {
        int gi = g * 256 + w * 32 + i;
        float4 v;
        if (mode == 0) {
            float4 b = *(const float4*)&g_buf[gi * EMB + f0];
            v.x = gg.x * (b.x - mm.x) * rr.x + bb.x;
            v.y = gg.y * (b.y - mm.y) * rr.y + bb.y;
            v.z = gg.z * (b.z - mm.z) * rr.z + bb.z;
            v.w = gg.w * (b.w - mm.w) * rr.w + bb.w;
        } else {
            float4 c = *(const float4*)&g_cur[gi * EMB + f0];
            unsigned mb = g_mask[gi];
            float4 b = {0.f, 0.f, 0.f, 0.f};
            if (mb) b = *(const float4*)&g_buf[gi * EMB + f0];
            float n0 = gg.x * (b.x - mm.x) * rr.x + bb.x;
            float n1 = gg.y * (b.y - mm.y) * rr.y + bb.y;
            float n2 = gg.z * (b.z - mm.z) * rr.z + bb.z;
            float n3 = gg.w * (b.w - mm.w) * rr.w + bb.w;
            v.x = 0.5f * c.x + 0.25f * n0;
            v.y = 0.5f * c.y + 0.25f * n1;
            v.z = 0.5f * c.z + 0.25f * n2;
            v.w = 0.5f * c.w + 0.25f * n3;
        }
        *(float4*)&g_cur[gi * EMB + f0] = v;
        float p0 = v.x * w0v.x + v.y * w0v.y + v.z * w0v.z + v.w * w0v.w;
        float p1 = v.x * w1v.x + v.y * w1v.y + v.z * w1v.z + v.w * w1v.w;
        float p2 = v.x * w2v.x + v.y * w2v.y + v.z * w2v.z + v.w * w2v.w;
        float p3 = v.x * w3v.x + v.y * w3v.y + v.z * w3v.z + v.w * w3v.w;
#pragma unroll
        for (int o = 16; o; o >>= 1) {
            p0 += __shfl_xor_sync(0xffffffffu, p0, o);
            p1 += __shfl_xor_sync(0xffffffffu, p1, o);
            p2 += __shfl_xor_sync(0xffffffffu, p2, o);
            p3 += __shfl_xor_sync(0xffffffffu, p3, o);
        }
        if (lane == 0) {
            int n = w * 32 + i;
            sc[0][n] = p0; sc[1][n] = p1; sc[2][n] = p2; sc[3][n] = p3;
        }
    }
    __syncthreads();

    unsigned mb = 0;
    for (int h = 0; h < NHD; h++) {
        float vv = sc[h][t];
        red[t] = vv; __syncthreads();
        for (int o = 128; o > 0; o >>= 1) {
            if (t < o) red[t] = fmaxf(red[t], red[t + o]);
            __syncthreads();
        }
        float m = red[0]; __syncthreads();
        float e = expf(vv - m);
        red[t] = e; __syncthreads();
        for (int o = 128; o > 0; o >>= 1) {
            if (t < o) red[t] += red[t + o];
            __syncthreads();
        }
        float s = red[0]; __syncthreads();
        float sm = e / (s + 1e-16f);
        float smax = 1.0f / (s + 1e-16f);
        float thr = fminf(smax - 1e-7f, min_score);
        if (sm > thr) mb |= (1u << h);
        g_sm[h * NN + g * 256 + t] = sm;
    }
    g_mask[g * 256 + t] = (unsigned char)mb;

    int flag = mb ? 1 : 0;
    iarr[t] = flag; __syncthreads();
    for (int off = 1; off < 256; off <<= 1) {
        int xv = (t >= off) ? iarr[t - off] : 0;
        __syncthreads(); iarr[t] += xv; __syncthreads();
    }
    if (flag) g_klist[g * 256 + iarr[t] - 1] = t | ((int)mb << 8);
    if (t == 255) g_kcnt[g] = iarr[255];
}

// ---------------- block head conv on kept nodes + fused BN partials ----------------
__global__ void k_head(const float* __restrict__ wrel, const float* __restrict__ wroot,
                       const float* __restrict__ bias) {
    int g = blockIdx.x, t = threadIdx.x;
    int cnt = g_kcnt[g];
    int h = t >> 5, j = t & 31;
    __shared__ float sCur[128];
    __shared__ float sAgg[NHD][128];
    float s_acc = 0.f, ss_acc = 0.f;
    for (int kk = 0; kk < cnt; kk++) {
        int pk = g_klist[g * 256 + kk];
        int i = g * 256 + (pk & 255);
        unsigned mb = (pk >> 8) & 15;
        sCur[t] = g_cur[i * EMB + t];
        int beg = g_rp[i], end = g_rp[i + 1];
#pragma unroll
        for (int hh = 0; hh < NHD; hh++) {
            if (!((mb >> hh) & 1)) continue;
            float m = -3.4e38f;
            bool any = false;
            for (int e = beg; e < end; e++) {
                int sidx = g_csrc[e];
                if ((g_mask[sidx] >> hh) & 1) {
                    m = fmaxf(m, g_cur[sidx * EMB + t] * g_sm[hh * NN + sidx]);
                    any = true;
                }
            }
            sAgg[hh][t] = any ? m : 0.f;
        }
        __syncthreads();
        float v = 0.f;
        if ((mb >> h) & 1) {
            float smv = g_sm[h * NN + i];
            float accv = bias[h * OUTD + j];
            const float* wr = &wrel[(h * OUTD + j) * EMB];
            const float* wo = &wroot[(h * OUTD + j) * EMB];
#pragma unroll 16
            for (int k = 0; k < EMB; k++)
                accv += wr[k] * sAgg[h][k] + wo[k] * (sCur[k] * smv);
            v = lrelu(accv);
        }
        g_buf[i * EMB + t] = v;
        s_acc += v; ss_acc += v * v;
        __syncthreads();
    }
    g_part[g * EMB + t] = s_acc;
    g_part2[g * EMB + t] = ss_acc;
}

// ---------------- fused classifier ----------------
__global__ void k_cls(const float* __restrict__ gW1, const float* __restrict__ gb1,
                      const float* __restrict__ gW2, const float* __restrict__ gb2,
                      const float* __restrict__ fW1, const float* __restrict__ fb1,
                      const float* __restrict__ fW2, const float* __restrict__ fb2,
                      float* __restrict__ out) {
    int g = blockIdx.x, t = threadIdx.x;
    __shared__ float gate_s[NHD][256];
    __shared__ float red[128];
    __shared__ float sCur[128];
    __shared__ float sPool[128];
    __shared__ float sLog[NHD];
    for (int idx = t; idx < NHD * 256; idx += 128)
        ((float*)gate_s)[idx] = NEG_INF;
    int cnt = g_kcnt[g];
    __syncthreads();

    for (int kk = 0; kk < cnt; kk++) {
        int pk = g_klist[g * 256 + kk];
        int n = pk & 255;
        unsigned mb = (pk >> 8) & 15;
        int i = g * 256 + n;
        sCur[t] = g_cur[i * EMB + t];
        __syncthreads();
        for (int c = 0; c < NHD; c++) {
            if (!((mb >> c) & 1)) continue;
            float smv = g_sm[c * NN + i];
            float accv = gb1[c * EMB + t];
            const float* wp = &gW1[(c * EMB + t) * EMB];
#pragma unroll 16
            for (int k = 0; k < EMB; k++) accv += wp[k] * (sCur[k] * smv);
            accv = lrelu(accv);
            red[t] = accv * gW2[c * EMB + t];
            __syncthreads();
            for (int o = 64; o > 0; o >>= 1) {
                if (t < o) red[t] += red[t + o];
                __syncthreads();
            }
            if (t == 0) gate_s[c][n] = red[0] + gb2[c];
            __syncthreads();
        }
        __syncthreads();
    }

    for (int c = 0; c < NHD; c++) {
        red[t] = fmaxf(gate_s[c][t], gate_s[c][t + 128]);
        __syncthreads();
        for (int o = 64; o > 0; o >>= 1) {
            if (t < o) red[t] = fmaxf(red[t], red[t + o]);
            __syncthreads();
        }
        float m = red[0]; __syncthreads();
        float e0 = expf(gate_s[c][t] - m);
        float e1 = expf(gate_s[c][t + 128] - m);
        red[t] = e0 + e1;
        __syncthreads();
        for (int o = 64; o > 0; o >>= 1) {
            if (t < o) red[t] += red[t + o];
            __syncthreads();
        }
        float s = red[0] + 1e-16f; __syncthreads();

        float pool = 0.f;
        for (int kk = 0; kk < cnt; kk++) {
            int pk = g_klist[g * 256 + kk];
            int n = pk & 255;
            unsigned mb = (pk >> 8) & 15;
            if (!((mb >> c) & 1)) continue;
            int i = g * 256 + n;
            float a = expf(gate_s[c][n] - m) / s;
            pool += a * g_sm[c * NN + i] * g_cur[i * EMB + t];
        }
        sPool[t] = pool;
        __syncthreads();
        float accv = fb1[c * EMB + t];
        const float* wp = &fW1[(c * EMB + t) * EMB];
#pragma unroll 16
        for (int k = 0; k < EMB; k++) accv += wp[k] * sPool[k];
        accv = lrelu(accv);
        red[t] = accv * fW2[c * EMB + t];
        __syncthreads();
        for (int o = 64; o > 0; o >>= 1) {
            if (t < o) red[t] += red[t + o];
            __syncthreads();
        }
        if (t == 0) sLog[c] = red[0] + fb2[c];
        __syncthreads();
    }

    if (t < NHD) {
        float m = fmaxf(fmaxf(sLog[0], sLog[1]), fmaxf(sLog[2], sLog[3]));
        float s = expf(sLog[0] - m) + expf(sLog[1] - m) + expf(sLog[2] - m) + expf(sLog[3] - m);
        out[g * NHD + t] = sLog[t] - m - logf(s);
    }
}

// ---------------- launch ----------------
extern "C" void kernel_launch(void* const* d_in, const int* in_sizes, int n_in,
                              void* d_out, int out_size) {
    const float* x       = (const float*)d_in[0];
    const int*   ei      = (const int*)d_in[1];
    const int*   src     = ei;
    const int*   dst     = ei + EE;
    const float* Wrel0   = (const float*)d_in[3];
    const float* Wroot0  = (const float*)d_in[4];
    const float* b0      = (const float*)d_in[5];
    const float* bn0g    = (const float*)d_in[6];
    const float* bn0b    = (const float*)d_in[7];
    const float* blk_pw  = (const float*)d_in[8];
    const float* blk_Wr  = (const float*)d_in[9];
    const float* blk_Wo  = (const float*)d_in[10];
    const float* blk_bb  = (const float*)d_in[11];
    const float* blk_bng = (const float*)d_in[12];
    const float* blk_bnb = (const float*)d_in[13];
    const float* cls_pw  = (const float*)d_in[14];
    const float* gW1     = (const float*)d_in[15];
    const float* gb1     = (const float*)d_in[16];
    const float* gW2     = (const float*)d_in[17];
    const float* gb2     = (const float*)d_in[18];
    const float* fW1     = (const float*)d_in[19];
    const float* fb1     = (const float*)d_in[20];
    const float* fW2     = (const float*)d_in[21];
    const float* fb2     = (const float*)d_in[22];
    float* out = (float*)d_out;

    void* degp = 0;
    cudaGetSymbolAddress(&degp, g_deg);

    // CSR by dst
    cudaMemsetAsync(degp, 0, NN * sizeof(int), 0);
    k_hist<<<EE / 256, 256>>>(dst);
    k_scanF<<<1, 1024>>>();
    k_scatter<<<EE / 256, 256>>>(src, dst);

    // conv0 (+ fused stats) -> statsR -> A0
    k_agg0<<<NN / 8, 256>>>(x);
    k_conv0<<<NN / 32, 256>>>(x, Wrel0, Wroot0, b0);
    k_statsR<<<EMB, 256>>>(NN / 32);
    k_A<<<BBG, 256>>>(0, bn0g, bn0b, blk_pw + 0 * NHD * EMB, 0.7f);

    // block 0
    k_head<<<BBG, 128>>>(blk_Wr, blk_Wo, blk_bb);
    k_statsR<<<EMB, 256>>>(BBG);
    k_A<<<BBG, 256>>>(1, blk_bng, blk_bnb, blk_pw + 1 * NHD * EMB, 0.7f);

    // block 1
    k_head<<<BBG, 128>>>(blk_Wr + NHD * OUTD * EMB, blk_Wo + NHD * OUTD * EMB, blk_bb + NHD * OUTD);
    k_statsR<<<EMB, 256>>>(BBG);
    k_A<<<BBG, 256>>>(1, blk_bng + EMB, blk_bnb + EMB, cls_pw, 0.8f);

    // classifier heads
    k_cls<<<BBG, 128>>>(gW1, gb1, gW2, gb2, fW1, fb1, fW2, fb2, out);
}

// round 8
// speedup vs baseline: 1.4080x; 1.3940x over previous
#include <cuda_runtime.h>

#define NN 65536
#define EE 524288
#define BBG 256
#define FEAT 64
#define EMB 128
#define NHD 4
#define OUTD 32
#define NEG_INF __int_as_float(0xff800000)

// ---------------- scratch ----------------
__device__ float g_aggf[NN * FEAT];
__device__ float g_buf[NN * EMB];
__device__ float g_cur[NN * EMB];
__device__ float g_sm[NHD * NN];
__device__ unsigned char g_mask[NN];
__device__ float g_part[2048 * EMB];
__device__ float g_part2[2048 * EMB];
__device__ float g_meanvar[2 * EMB];
__device__ int g_klist[BBG * 256];
__device__ int g_kcnt[BBG];
__device__ int g_deg[NN];
__device__ int g_rp[NN + 1];
__device__ int g_cursor[NN];
__device__ int g_csrc[EE];
__device__ int g_bsum[256];
__device__ int g_boff[256];

__device__ __forceinline__ float lrelu(float v) { return v > 0.f ? v : 0.01f * v; }

// ---------------- CSR build (by dst); g_deg zeroed by cudaMemsetAsync ----------------
__global__ void k_hist(const int* __restrict__ dst) {
    int e = blockIdx.x * blockDim.x + threadIdx.x;
    if (e < EE) atomicAdd(&g_deg[dst[e]], 1);
}
__global__ void k_scan1() {
    int b = blockIdx.x, t = threadIdx.x;
    int v = g_deg[b * 256 + t];
    __shared__ int a[256];
    a[t] = v; __syncthreads();
    for (int off = 1; off < 256; off <<= 1) {
        int x = (t >= off) ? a[t - off] : 0;
        __syncthreads(); a[t] += x; __syncthreads();
    }
    g_rp[b * 256 + t] = a[t] - v;
    if (t == 255) g_bsum[b] = a[t];
}
__global__ void k_scan2() {
    int t = threadIdx.x;
    int v = g_bsum[t];
    __shared__ int a[256];
    a[t] = v; __syncthreads();
    for (int off = 1; off < 256; off <<= 1) {
        int x = (t >= off) ? a[t - off] : 0;
        __syncthreads(); a[t] += x; __syncthreads();
    }
    g_boff[t] = a[t] - v;
}
__global__ void k_scan3() {
    int i = blockIdx.x * blockDim.x + threadIdx.x;
    if (i < NN) {
        int r = g_rp[i] + g_boff[i >> 8];
        g_rp[i] = r;
        g_cursor[i] = r;
        if (i == 0) g_rp[NN] = EE;
    }
}
__global__ void k_scatter(const int* __restrict__ src, const int* __restrict__ dst) {
    int e = blockIdx.x * blockDim.x + threadIdx.x;
    if (e < EE) {
        int p = atomicAdd(&g_cursor[dst[e]], 1);
        g_csrc[p] = src[e];
    }
}

// ---------------- conv0 max aggregation (warp per node, 2-edge ILP) ----------------
__global__ void k_agg0(const float* __restrict__ x) {
    int wi = (blockIdx.x * blockDim.x + threadIdx.x) >> 5;
    if (wi >= NN) return;
    int lane = threadIdx.x & 31;
    int beg = g_rp[wi], end = g_rp[wi + 1];
    float m0 = -3.4e38f, m1 = -3.4e38f;
    float n0 = -3.4e38f, n1 = -3.4e38f;
    int e = beg;
    for (; e + 1 < end; e += 2) {
        int s0 = g_csrc[e], s1 = g_csrc[e + 1];
        m0 = fmaxf(m0, x[s0 * FEAT + lane]);
        m1 = fmaxf(m1, x[s0 * FEAT + 32 + lane]);
        n0 = fmaxf(n0, x[s1 * FEAT + lane]);
        n1 = fmaxf(n1, x[s1 * FEAT + 32 + lane]);
    }
    if (e < end) {
        int s0 = g_csrc[e];
        m0 = fmaxf(m0, x[s0 * FEAT + lane]);
        m1 = fmaxf(m1, x[s0 * FEAT + 32 + lane]);
    }
    m0 = fmaxf(m0, n0);
    m1 = fmaxf(m1, n1);
    if (beg == end) { m0 = 0.f; m1 = 0.f; }
    g_aggf[wi * FEAT + lane] = m0;
    g_aggf[wi * FEAT + 32 + lane] = m1;
}

// ---------------- conv0 GEMM + fused BN partials (R4-proven tile) ----------------
__global__ void k_conv0(const float* __restrict__ x, const float* __restrict__ wrel,
                        const float* __restrict__ wroot, const float* __restrict__ b0) {
    __shared__ float sW[64 * 132];
    __shared__ float sIn[64 * 36];
    int tx = threadIdx.x;
    int og = tx & 31;
    int ng = tx >> 5;
    int nbase = blockIdx.x * 32;

    float acc[4][4];
#pragma unroll
    for (int p = 0; p < 4; p++)
#pragma unroll
        for (int q = 0; q < 4; q++) acc[p][q] = 0.f;

    for (int c = 0; c < 2; c++) {
        const float* W = c ? wroot : wrel;
        const float* In = c ? x : g_aggf;
#pragma unroll
        for (int r = 0; r < 32; r++) {
            int lin = r * 256 + tx;
            int j = lin >> 6, k = lin & 63;
            sW[k * 132 + j] = W[j * 64 + k];
        }
#pragma unroll
        for (int r = 0; r < 8; r++) {
            int lin = r * 256 + tx;
            int n = lin >> 6, k = lin & 63;
            sIn[k * 36 + n] = In[(nbase + n) * 64 + k];
        }
        __syncthreads();
#pragma unroll 16
        for (int k = 0; k < 64; k++) {
            float4 wv = *(const float4*)&sW[k * 132 + og * 4];
            float4 iv = *(const float4*)&sIn[k * 36 + ng * 4];
            acc[0][0] += iv.x * wv.x; acc[0][1] += iv.x * wv.y; acc[0][2] += iv.x * wv.z; acc[0][3] += iv.x * wv.w;
            acc[1][0] += iv.y * wv.x; acc[1][1] += iv.y * wv.y; acc[1][2] += iv.y * wv.z; acc[1][3] += iv.y * wv.w;
            acc[2][0] += iv.z * wv.x; acc[2][1] += iv.z * wv.y; acc[2][2] += iv.z * wv.z; acc[2][3] += iv.z * wv.w;
            acc[3][0] += iv.w * wv.x; acc[3][1] += iv.w * wv.y; acc[3][2] += iv.w * wv.z; acc[3][3] += iv.w * wv.w;
        }
        __syncthreads();
    }
    int j0 = og * 4;
    float4 bb = *(const float4*)&b0[j0];
    float s[4] = {0, 0, 0, 0}, ss[4] = {0, 0, 0, 0};
#pragma unroll
    for (int p = 0; p < 4; p++) {
        int node = nbase + ng * 4 + p;
        float v0 = lrelu(acc[p][0] + bb.x);
        float v1 = lrelu(acc[p][1] + bb.y);
        float v2 = lrelu(acc[p][2] + bb.z);
        float v3 = lrelu(acc[p][3] + bb.w);
        float4 o = {v0, v1, v2, v3};
        *(float4*)&g_buf[node * EMB + j0] = o;
        s[0] += v0; ss[0] += v0 * v0;
        s[1] += v1; ss[1] += v1 * v1;
        s[2] += v2; ss[2] += v2 * v2;
        s[3] += v3; ss[3] += v3 * v3;
    }
    float2* pr = (float2*)sW;
#pragma unroll
    for (int q = 0; q < 4; q++)
        pr[(j0 + q) * 8 + ng] = make_float2(s[q], ss[q]);
    __syncthreads();
    if (tx < 128) {
        float a = 0.f, a2 = 0.f;
#pragma unroll
        for (int w = 0; w < 8; w++) {
            float2 v = pr[tx * 8 + w];
            a += v.x; a2 += v.y;
        }
        g_part[blockIdx.x * EMB + tx] = a;
        g_part2[blockIdx.x * EMB + tx] = a2;
    }
}

// ---------------- reduce partials ----------------
__global__ void k_statsR(int P) {
    int f = blockIdx.x, t = threadIdx.x;
    float s = 0.f, ss = 0.f;
    for (int p = t; p < P; p += 256) {
        s += g_part[p * EMB + f];
        ss += g_part2[p * EMB + f];
    }
    __shared__ float r1[256], r2[256];
    r1[t] = s; r2[t] = ss;
    __syncthreads();
    for (int o = 128; o > 0; o >>= 1) {
        if (t < o) { r1[t] += r1[t + o]; r2[t] += r2[t + o]; }
        __syncthreads();
    }
    if (t == 0) {
        float mean = r1[0] * (1.f / NN);
        float var = r2[0] * (1.f / NN) - mean * mean;
        g_meanvar[f] = mean;
        g_meanvar[EMB + f] = 1.f / sqrtf(var + 1e-5f);
    }
}

// ---------------- fused: BN/update + scores + softmax(2 head-pairs in parallel) + keep + compact ----------------
// 512 threads: phase1 = 16 warps x 16 nodes; phase2 = two 256-thread groups, one head-pair each.
__global__ void __launch_bounds__(512) k_A(int mode, const float* __restrict__ gam,
                    const float* __restrict__ bet,
                    const float* __restrict__ w4, float min_score) {
    int g = blockIdx.x, t = threadIdx.x;
    int w = t >> 5, lane = t & 31;
    __shared__ float sG[128], sBt[128], sMu[128], sRs[128];
    __shared__ float sW[4 * 128];
    __shared__ float sc[4][256];
    __shared__ float red[2][256];
    __shared__ int smask2[2][256];
    __shared__ int iarr[256];
    if (t < 128) {
        sG[t] = gam[t]; sBt[t] = bet[t];
        sMu[t] = g_meanvar[t]; sRs[t] = g_meanvar[EMB + t];
    }
    sW[t] = w4[t];                 // 512 = 4*128 exactly
    __syncthreads();

    int f0 = lane * 4;
    float4 gg = *(float4*)&sG[f0], bb = *(float4*)&sBt[f0];
    float4 mm = *(float4*)&sMu[f0], rr = *(float4*)&sRs[f0];
    float4 w0v = *(float4*)&sW[0 * 128 + f0];
    float4 w1v = *(float4*)&sW[1 * 128 + f0];
    float4 w2v = *(float4*)&sW[2 * 128 + f0];
    float4 w3v = *(float4*)&sW[3 * 128 + f0];

    // phase 1: warp w handles nodes [w*16, w*16+16)
    for (int i = 0; i < 16; i++) {
        int n = w * 16 + i;
        int gi = g * 256 + n;
        float4 v;
        if (mode == 0) {
            float4 b = *(const float4*)&g_buf[gi * EMB + f0];
            v.x = gg.x * (b.x - mm.x) * rr.x + bb.x;
            v.y = gg.y * (b.y - mm.y) * rr.y + bb.y;
            v.z = gg.z * (b.z - mm.z) * rr.z + bb.z;
            v.w = gg.w * (b.w - mm.w) * rr.w + bb.w;
        } else {
            float4 c = *(const float4*)&g_cur[gi * EMB + f0];
            unsigned mbp = g_mask[gi];
            float4 b = {0.f, 0.f, 0.f, 0.f};
            if (mbp) b = *(const float4*)&g_buf[gi * EMB + f0];
            float n0 = gg.x * (b.x - mm.x) * rr.x + bb.x;
            float n1 = gg.y * (b.y - mm.y) * rr.y + bb.y;
            float n2 = gg.z * (b.z - mm.z) * rr.z + bb.z;
            float n3 = gg.w * (b.w - mm.w) * rr.w + bb.w;
            v.x = 0.5f * c.x + 0.25f * n0;
            v.y = 0.5f * c.y + 0.25f * n1;
            v.z = 0.5f * c.z + 0.25f * n2;
            v.w = 0.5f * c.w + 0.25f * n3;
        }
        *(float4*)&g_cur[gi * EMB + f0] = v;
        float p0 = v.x * w0v.x + v.y * w0v.y + v.z * w0v.z + v.w * w0v.w;
        float p1 = v.x * w1v.x + v.y * w1v.y + v.z * w1v.z + v.w * w1v.w;
        float p2 = v.x * w2v.x + v.y * w2v.y + v.z * w2v.z + v.w * w2v.w;
        float p3 = v.x * w3v.x + v.y * w3v.y + v.z * w3v.z + v.w * w3v.w;
#pragma unroll
        for (int o = 16; o; o >>= 1) {
            p0 += __shfl_xor_sync(0xffffffffu, p0, o);
            p1 += __shfl_xor_sync(0xffffffffu, p1, o);
            p2 += __shfl_xor_sync(0xffffffffu, p2, o);
            p3 += __shfl_xor_sync(0xffffffffu, p3, o);
        }
        if (lane == 0) {
            sc[0][n] = p0; sc[1][n] = p1; sc[2][n] = p2; sc[3][n] = p3;
        }
    }
    __syncthreads();

    // phase 2: group g2 (0/1) handles heads {g2*2, g2*2+1} for node tn
    int g2 = t >> 8;
    int tn = t & 255;
    unsigned mbits = 0;
#pragma unroll
    for (int hh = 0; hh < 2; hh++) {
        int h = g2 * 2 + hh;
        float vv = sc[h][tn];
        red[g2][tn] = vv; __syncthreads();
        for (int o = 128; o > 0; o >>= 1) {
            if (tn < o) red[g2][tn] = fmaxf(red[g2][tn], red[g2][tn + o]);
            __syncthreads();
        }
        float m = red[g2][0]; __syncthreads();
        float e = expf(vv - m);
        red[g2][tn] = e; __syncthreads();
        for (int o = 128; o > 0; o >>= 1) {
            if (tn < o) red[g2][tn] += red[g2][tn + o];
            __syncthreads();
        }
        float s = red[g2][0]; __syncthreads();
        float sm = e / (s + 1e-16f);
        float smax = 1.0f / (s + 1e-16f);
        float thr = fminf(smax - 1e-7f, min_score);
        if (sm > thr) mbits |= (1u << hh);
        g_sm[h * NN + g * 256 + tn] = sm;
    }
    smask2[g2][tn] = (int)mbits;
    __syncthreads();

    // phase 3: merge masks + compact (t<256 active; barriers uniform)
    int mb = 0, flag = 0;
    if (t < 256) {
        mb = smask2[0][t] | (smask2[1][t] << 2);
        g_mask[g * 256 + t] = (unsigned char)mb;
        flag = mb ? 1 : 0;
        iarr[t] = flag;
    }
    __syncthreads();
    for (int off = 1; off < 256; off <<= 1) {
        int xv = 0;
        if (t < 256 && t >= off) xv = iarr[t - off];
        __syncthreads();
        if (t < 256) iarr[t] += xv;
        __syncthreads();
    }
    if (t < 256 && flag) g_klist[g * 256 + iarr[t] - 1] = t | (mb << 8);
    if (t == 255) g_kcnt[g] = iarr[255];
}

// ---------------- block head conv on kept nodes + fused BN partials ----------------
__global__ void k_head(const float* __restrict__ wrel, const float* __restrict__ wroot,
                       const float* __restrict__ bias) {
    int g = blockIdx.x, t = threadIdx.x;
    int cnt = g_kcnt[g];
    int h = t >> 5, j = t & 31;
    __shared__ float sCur[128];
    __shared__ float sAgg[NHD][128];
    float s_acc = 0.f, ss_acc = 0.f;
    for (int kk = 0; kk < cnt; kk++) {
        int pk = g_klist[g * 256 + kk];
        int i = g * 256 + (pk & 255);
        unsigned mb = (pk >> 8) & 15;
        sCur[t] = g_cur[i * EMB + t];
        int beg = g_rp[i], end = g_rp[i + 1];
#pragma unroll
        for (int hh = 0; hh < NHD; hh++) {
            if (!((mb >> hh) & 1)) continue;
            float m = -3.4e38f;
            bool any = false;
            for (int e = beg; e < end; e++) {
                int sidx = g_csrc[e];
                if ((g_mask[sidx] >> hh) & 1) {
                    m = fmaxf(m, g_cur[sidx * EMB + t] * g_sm[hh * NN + sidx]);
                    any = true;
                }
            }
            sAgg[hh][t] = any ? m : 0.f;
        }
        __syncthreads();
        float v = 0.f;
        if ((mb >> h) & 1) {
            float smv = g_sm[h * NN + i];
            float accv = bias[h * OUTD + j];
            const float* wr = &wrel[(h * OUTD + j) * EMB];
            const float* wo = &wroot[(h * OUTD + j) * EMB];
#pragma unroll 16
            for (int k = 0; k < EMB; k++)
                accv += wr[k] * sAgg[h][k] + wo[k] * (sCur[k] * smv);
            v = lrelu(accv);
        }
        g_buf[i * EMB + t] = v;
        s_acc += v; ss_acc += v * v;
        __syncthreads();
    }
    g_part[g * EMB + t] = s_acc;
    g_part2[g * EMB + t] = ss_acc;
}

// ---------------- fused classifier ----------------
__global__ void k_cls(const float* __restrict__ gW1, const float* __restrict__ gb1,
                      const float* __restrict__ gW2, const float* __restrict__ gb2,
                      const float* __restrict__ fW1, const float* __restrict__ fb1,
                      const float* __restrict__ fW2, const float* __restrict__ fb2,
                      float* __restrict__ out) {
    int g = blockIdx.x, t = threadIdx.x;
    __shared__ float gate_s[NHD][256];
    __shared__ float red[128];
    __shared__ float sCur[128];
    __shared__ float sPool[128];
    __shared__ float sLog[NHD];
    for (int idx = t; idx < NHD * 256; idx += 128)
        ((float*)gate_s)[idx] = NEG_INF;
    int cnt = g_kcnt[g];
    __syncthreads();

    for (int kk = 0; kk < cnt; kk++) {
        int pk = g_klist[g * 256 + kk];
        int n = pk & 255;
        unsigned mb = (pk >> 8) & 15;
        int i = g * 256 + n;
        sCur[t] = g_cur[i * EMB + t];
        __syncthreads();
        for (int c = 0; c < NHD; c++) {
            if (!((mb >> c) & 1)) continue;
            float smv = g_sm[c * NN + i];
            float accv = gb1[c * EMB + t];
            const float* wp = &gW1[(c * EMB + t) * EMB];
#pragma unroll 16
            for (int k = 0; k < EMB; k++) accv += wp[k] * (sCur[k] * smv);
            accv = lrelu(accv);
            red[t] = accv * gW2[c * EMB + t];
            __syncthreads();
            for (int o = 64; o > 0; o >>= 1) {
                if (t < o) red[t] += red[t + o];
                __syncthreads();
            }
            if (t == 0) gate_s[c][n] = red[0] + gb2[c];
            __syncthreads();
        }
        __syncthreads();
    }

    for (int c = 0; c < NHD; c++) {
        red[t] = fmaxf(gate_s[c][t], gate_s[c][t + 128]);
        __syncthreads();
        for (int o = 64; o > 0; o >>= 1) {
            if (t < o) red[t] = fmaxf(red[t], red[t + o]);
            __syncthreads();
        }
        float m = red[0]; __syncthreads();
        float e0 = expf(gate_s[c][t] - m);
        float e1 = expf(gate_s[c][t + 128] - m);
        red[t] = e0 + e1;
        __syncthreads();
        for (int o = 64; o > 0; o >>= 1) {
            if (t < o) red[t] += red[t + o];
            __syncthreads();
        }
        float s = red[0] + 1e-16f; __syncthreads();

        float pool = 0.f;
        for (int kk = 0; kk < cnt; kk++) {
            int pk = g_klist[g * 256 + kk];
            int n = pk & 255;
            unsigned mb = (pk >> 8) & 15;
            if (!((mb >> c) & 1)) continue;
            int i = g * 256 + n;
            float a = expf(gate_s[c][n] - m) / s;
            pool += a * g_sm[c * NN + i] * g_cur[i * EMB + t];
        }
        sPool[t] = pool;
        __syncthreads();
        float accv = fb1[c * EMB + t];
        const float* wp = &fW1[(c * EMB + t) * EMB];
#pragma unroll 16
        for (int k = 0; k < EMB; k++) accv += wp[k] * sPool[k];
        accv = lrelu(accv);
        red[t] = accv * fW2[c * EMB + t];
        __syncthreads();
        for (int o = 64; o > 0; o >>= 1) {
            if (t < o) red[t] += red[t + o];
            __syncthreads();
        }
        if (t == 0) sLog[c] = red[0] + fb2[c];
        __syncthreads();
    }

    if (t < NHD) {
        float m = fmaxf(fmaxf(sLog[0], sLog[1]), fmaxf(sLog[2], sLog[3]));
        float s = expf(sLog[0] - m) + expf(sLog[1] - m) + expf(sLog[2] - m) + expf(sLog[3] - m);
        out[g * NHD + t] = sLog[t] - m - logf(s);
    }
}

// ---------------- launch ----------------
extern "C" void kernel_launch(void* const* d_in, const int* in_sizes, int n_in,
                              void* d_out, int out_size) {
    const float* x       = (const float*)d_in[0];
    const int*   ei      = (const int*)d_in[1];
    const int*   src     = ei;
    const int*   dst     = ei + EE;
    const float* Wrel0   = (const float*)d_in[3];
    const float* Wroot0  = (const float*)d_in[4];
    const float* b0      = (const float*)d_in[5];
    const float* bn0g    = (const float*)d_in[6];
    const float* bn0b    = (const float*)d_in[7];
    const float* blk_pw  = (const float*)d_in[8];
    const float* blk_Wr  = (const float*)d_in[9];
    const float* blk_Wo  = (const float*)d_in[10];
    const float* blk_bb  = (const float*)d_in[11];
    const float* blk_bng = (const float*)d_in[12];
    const float* blk_bnb = (const float*)d_in[13];
    const float* cls_pw  = (const float*)d_in[14];
    const float* gW1     = (const float*)d_in[15];
    const float* gb1     = (const float*)d_in[16];
    const float* gW2     = (const float*)d_in[17];
    const float* gb2     = (const float*)d_in[18];
    const float* fW1     = (const float*)d_in[19];
    const float* fb1     = (const float*)d_in[20];
    const float* fW2     = (const float*)d_in[21];
    const float* fb2     = (const float*)d_in[22];
    float* out = (float*)d_out;

    void* degp = 0;
    cudaGetSymbolAddress(&degp, g_deg);

    // CSR by dst (coalesced multi-block scans — R4-proven)
    cudaMemsetAsync(degp, 0, NN * sizeof(int), 0);
    k_hist<<<EE / 256, 256>>>(dst);
    k_scan1<<<256, 256>>>();
    k_scan2<<<1, 256>>>();
    k_scan3<<<256, 256>>>();
    k_scatter<<<EE / 256, 256>>>(src, dst);

    // conv0 (+ fused stats) -> statsR -> A0
    k_agg0<<<NN / 8, 256>>>(x);
    k_conv0<<<NN / 32, 256>>>(x, Wrel0, Wroot0, b0);
    k_statsR<<<EMB, 256>>>(NN / 32);
    k_A<<<BBG, 512>>>(0, bn0g, bn0b, blk_pw + 0 * NHD * EMB, 0.7f);

    // block 0
    k_head<<<BBG, 128>>>(blk_Wr, blk_Wo, blk_bb);
    k_statsR<<<EMB, 256>>>(BBG);
    k_A<<<BBG, 512>>>(1, blk_bng, blk_bnb, blk_pw + 1 * NHD * EMB, 0.7f);

    // block 1
    k_head<<<BBG, 128>>>(blk_Wr + NHD * OUTD * EMB, blk_Wo + NHD * OUTD * EMB, blk_bb + NHD * OUTD);
    k_statsR<<<EMB, 256>>>(BBG);
    k_A<<<BBG, 512>>>(1, blk_bng + EMB, blk_bnb + EMB, cls_pw, 0.8f);

    // classifier heads
    k_cls<<<BBG, 128>>>(gW1, gb1, gW2, gb2, fW1, fb1, fW2, fb2, out);
}

// round 10
// speedup vs baseline: 1.5397x; 1.0935x over previous
#include <cuda_runtime.h>
#include <cstdint>

#define NN 65536
#define EE 524288
#define BBG 256
#define FEAT 64
#define EMB 128
#define NHD 4
#define OUTD 32
#define NEG_INF __int_as_float(0xff800000)

// ---------------- scratch ----------------
__device__ float g_aggf[NN * FEAT];
__device__ float g_buf[NN * EMB];
__device__ float g_cur[NN * EMB];
__device__ float g_sm[NHD * NN];
__device__ unsigned char g_mask[NN];
__device__ float g_part[2048 * EMB];
__device__ float g_part2[2048 * EMB];
__device__ float g_meanvar[2 * EMB];
__device__ int g_klist[BBG * 256];
__device__ int g_kcnt[BBG];
__device__ int g_deg[NN];
__device__ int g_rp[NN + 1];
__device__ int g_cursor[NN];
__device__ int g_csrc[EE];
__device__ int g_bsum[256];
__device__ int g_boff[256];

__device__ __forceinline__ float lrelu(float v) { return v > 0.f ? v : 0.01f * v; }

// ---------------- CSR build ----------------
__global__ void k_hist(const int* __restrict__ dst) {
    int e = blockIdx.x * blockDim.x + threadIdx.x;
    if (e < EE) atomicAdd(&g_deg[dst[e]], 1);
}
__global__ void k_scan1() {
    int b = blockIdx.x, t = threadIdx.x;
    int v = g_deg[b * 256 + t];
    __shared__ int a[256];
    a[t] = v; __syncthreads();
    for (int off = 1; off < 256; off <<= 1) {
        int x = (t >= off) ? a[t - off] : 0;
        __syncthreads(); a[t] += x; __syncthreads();
    }
    g_rp[b * 256 + t] = a[t] - v;
    if (t == 255) g_bsum[b] = a[t];
}
__global__ void k_scan2() {
    int t = threadIdx.x;
    int v = g_bsum[t];
    __shared__ int a[256];
    a[t] = v; __syncthreads();
    for (int off = 1; off < 256; off <<= 1) {
        int x = (t >= off) ? a[t - off] : 0;
        __syncthreads(); a[t] += x; __syncthreads();
    }
    g_boff[t] = a[t] - v;
}
__global__ void k_scan3() {
    int i = blockIdx.x * blockDim.x + threadIdx.x;
    if (i < NN) {
        int r = g_rp[i] + g_boff[i >> 8];
        g_rp[i] = r;
        g_cursor[i] = r;
        if (i == 0) g_rp[NN] = EE;
    }
}
__global__ void k_scatter(const int* __restrict__ src, const int* __restrict__ dst) {
    int e = blockIdx.x * blockDim.x + threadIdx.x;
    if (e < EE) {
        int p = atomicAdd(&g_cursor[dst[e]], 1);
        g_csrc[p] = src[e];
    }
}

// ---------------- conv0 max aggregation (warp per node, 2-edge ILP) ----------------
__global__ void k_agg0(const float* __restrict__ x) {
    int wi = (blockIdx.x * blockDim.x + threadIdx.x) >> 5;
    if (wi >= NN) return;
    int lane = threadIdx.x & 31;
    int beg = g_rp[wi], end = g_rp[wi + 1];
    float m0 = -3.4e38f, m1 = -3.4e38f;
    float n0 = -3.4e38f, n1 = -3.4e38f;
    int e = beg;
    for (; e + 1 < end; e += 2) {
        int s0 = g_csrc[e], s1 = g_csrc[e + 1];
        m0 = fmaxf(m0, x[s0 * FEAT + lane]);
        m1 = fmaxf(m1, x[s0 * FEAT + 32 + lane]);
        n0 = fmaxf(n0, x[s1 * FEAT + lane]);
        n1 = fmaxf(n1, x[s1 * FEAT + 32 + lane]);
    }
    if (e < end) {
        int s0 = g_csrc[e];
        m0 = fmaxf(m0, x[s0 * FEAT + lane]);
        m1 = fmaxf(m1, x[s0 * FEAT + 32 + lane]);
    }
    m0 = fmaxf(m0, n0);
    m1 = fmaxf(m1, n1);
    if (beg == end) { m0 = 0.f; m1 = 0.f; }
    g_aggf[wi * FEAT + lane] = m0;
    g_aggf[wi * FEAT + 32 + lane] = m1;
}

// ---------------- conv0 via mma.sync tf32x3 ----------------
__device__ __forceinline__ uint32_t f2tf(float v) {
    uint32_t r;
    asm("cvt.rna.tf32.f32 %0, %1;" : "=r"(r) : "f"(v));
    return r;
}
#define MMA_TF32(c, a0, a1, a2, a3, b0, b1) \
    asm volatile("mma.sync.aligned.m16n8k8.row.col.f32.tf32.tf32.f32 " \
                 "{%0,%1,%2,%3}, {%4,%5,%6,%7}, {%8,%9}, {%0,%1,%2,%3};" \
                 : "+f"((c)[0]), "+f"((c)[1]), "+f"((c)[2]), "+f"((c)[3]) \
                 : "r"(a0), "r"(a1), "r"(a2), "r"(a3), "r"(b0), "r"(b1))

// block: 64 nodes x 128 outs, K=128 (agg||x vs Wrel||Wroot). 8 warps, warp = 32x32.
#define PITCH 132
#define DSMEM ((64 * PITCH + 128 * PITCH) * 4)
__global__ void __launch_bounds__(256) k_convM(const float* __restrict__ x,
                                               const float* __restrict__ wrel,
                                               const float* __restrict__ wroot,
                                               const float* __restrict__ b0) {
    extern __shared__ float smf[];
    float* sIn = smf;                 // [64][PITCH], cols 0:64 agg, 64:128 x
    float* sW = smf + 64 * PITCH;     // [128][PITCH], cols 0:64 wrel, 64:128 wroot
    __shared__ float2 sStat[8][32];
    int tx = threadIdx.x;
    int w = tx >> 5, lane = tx & 31;
    int gid = lane >> 2, tig = lane & 3;
    int nbase = blockIdx.x * 64;

    // stage In: 64 rows x 32 float4 chunks
#pragma unroll
    for (int it = 0; it < 8; it++) {
        int c = it * 256 + tx;
        int row = c >> 5, q = c & 31;
        float4 v = (q < 16) ? *(const float4*)&g_aggf[(nbase + row) * 64 + q * 4]
                            : *(const float4*)&x[(nbase + row) * 64 + (q - 16) * 4];
        *(float4*)&sIn[row * PITCH + q * 4] = v;
    }
    // stage W: 128 rows x 32 chunks
#pragma unroll
    for (int it = 0; it < 16; it++) {
        int c = it * 256 + tx;
        int row = c >> 5, q = c & 31;
        float4 v = (q < 16) ? *(const float4*)&wrel[row * 64 + q * 4]
                            : *(const float4*)&wroot[row * 64 + (q - 16) * 4];
        *(float4*)&sW[row * PITCH + q * 4] = v;
    }
    __syncthreads();

    int mrow0 = (w & 1) * 32;     // warp's node offset in block
    int ocol0 = (w >> 1) * 32;    // warp's out offset

    float acc[2][4][4];
#pragma unroll
    for (int mt = 0; mt < 2; mt++)
#pragma unroll
        for (int nt = 0; nt < 4; nt++)
#pragma unroll
            for (int r = 0; r < 4; r++) acc[mt][nt][r] = 0.f;

    for (int kb = 0; kb < 128; kb += 8) {
        uint32_t ahi[2][4], alo[2][4], bhi[4][2], blo[4][2];
#pragma unroll
        for (int mt = 0; mt < 2; mt++) {
            int rb = mrow0 + mt * 16;
            float v0 = sIn[(rb + gid) * PITCH + kb + tig];
            float v1 = sIn[(rb + gid + 8) * PITCH + kb + tig];
            float v2 = sIn[(rb + gid) * PITCH + kb + tig + 4];
            float v3 = sIn[(rb + gid + 8) * PITCH + kb + tig + 4];
            ahi[mt][0] = f2tf(v0); alo[mt][0] = f2tf(v0 - __uint_as_float(ahi[mt][0]));
            ahi[mt][1] = f2tf(v1); alo[mt][1] = f2tf(v1 - __uint_as_float(ahi[mt][1]));
            ahi[mt][2] = f2tf(v2); alo[mt][2] = f2tf(v2 - __uint_as_float(ahi[mt][2]));
            ahi[mt][3] = f2tf(v3); alo[mt][3] = f2tf(v3 - __uint_as_float(ahi[mt][3]));
        }
#pragma unroll
        for (int nt = 0; nt < 4; nt++) {
            int n = ocol0 + nt * 8 + gid;
            float u0 = sW[n * PITCH + kb + tig];
            float u1 = sW[n * PITCH + kb + tig + 4];
            bhi[nt][0] = f2tf(u0); blo[nt][0] = f2tf(u0 - __uint_as_float(bhi[nt][0]));
            bhi[nt][1] = f2tf(u1); blo[nt][1] = f2tf(u1 - __uint_as_float(bhi[nt][1]));
        }
#pragma unroll
        for (int mt = 0; mt < 2; mt++)
#pragma unroll
            for (int nt = 0; nt < 4; nt++) {
                MMA_TF32(acc[mt][nt], ahi[mt][0], ahi[mt][1], ahi[mt][2], ahi[mt][3],
                         bhi[nt][0], bhi[nt][1]);
                MMA_TF32(acc[mt][nt], ahi[mt][0], ahi[mt][1], ahi[mt][2], ahi[mt][3],
                         blo[nt][0], blo[nt][1]);
                MMA_TF32(acc[mt][nt], alo[mt][0], alo[mt][1], alo[mt][2], alo[mt][3],
                         bhi[nt][0], bhi[nt][1]);
            }
    }

    // epilogue: bias + lrelu + store + per-column stats
    float s0[4] = {0, 0, 0, 0}, s1[4] = {0, 0, 0, 0};
    float q0[4] = {0, 0, 0, 0}, q1[4] = {0, 0, 0, 0};
#pragma unroll
    for (int nt = 0; nt < 4; nt++) {
        int out0 = ocol0 + nt * 8 + 2 * tig;
        float bv0 = __ldg(&b0[out0]);
        float bv1 = __ldg(&b0[out0 + 1]);
#pragma unroll
        for (int mt = 0; mt < 2; mt++) {
            int node = nbase + mrow0 + mt * 16 + gid;
            float v00 = lrelu(acc[mt][nt][0] + bv0);
            float v01 = lrelu(acc[mt][nt][1] + bv1);
            float v10 = lrelu(acc[mt][nt][2] + bv0);
            float v11 = lrelu(acc[mt][nt][3] + bv1);
            *(float2*)&g_buf[node * EMB + out0] = make_float2(v00, v01);
            *(float2*)&g_buf[(node + 8) * EMB + out0] = make_float2(v10, v11);
            s0[nt] += v00 + v10; q0[nt] += v00 * v00 + v10 * v10;
            s1[nt] += v01 + v11; q1[nt] += v01 * v01 + v11 * v11;
        }
    }
    // reduce across the 8 groups (lanes sharing tig)
#pragma unroll
    for (int o = 4; o <= 16; o <<= 1) {
#pragma unroll
        for (int nt = 0; nt < 4; nt++) {
            s0[nt] += __shfl_xor_sync(0xffffffffu, s0[nt], o);
            s1[nt] += __shfl_xor_sync(0xffffffffu, s1[nt], o);
            q0[nt] += __shfl_xor_sync(0xffffffffu, q0[nt], o);
            q1[nt] += __shfl_xor_sync(0xffffffffu, q1[nt], o);
        }
    }
    if (lane < 4) {
#pragma unroll
        for (int nt = 0; nt < 4; nt++) {
            sStat[w][nt * 8 + 2 * lane] = make_float2(s0[nt], q0[nt]);
            sStat[w][nt * 8 + 2 * lane + 1] = make_float2(s1[nt], q1[nt]);
        }
    }
    __syncthreads();
    if (tx < 128) {
        int oq = tx >> 5, idx = tx & 31;
        float2 p1 = sStat[2 * oq][idx];
        float2 p2 = sStat[2 * oq + 1][idx];
        g_part[blockIdx.x * EMB + tx] = p1.x + p2.x;
        g_part2[blockIdx.x * EMB + tx] = p1.y + p2.y;
    }
}

// ---------------- reduce partials ----------------
__global__ void k_statsR(int P) {
    int f = blockIdx.x, t = threadIdx.x;
    float s = 0.f, ss = 0.f;
    for (int p = t; p < P; p += 256) {
        s += g_part[p * EMB + f];
        ss += g_part2[p * EMB + f];
    }
    __shared__ float r1[256], r2[256];
    r1[t] = s; r2[t] = ss;
    __syncthreads();
    for (int o = 128; o > 0; o >>= 1) {
        if (t < o) { r1[t] += r1[t + o]; r2[t] += r2[t + o]; }
        __syncthreads();
    }
    if (t == 0) {
        float mean = r1[0] * (1.f / NN);
        float var = r2[0] * (1.f / NN) - mean * mean;
        g_meanvar[f] = mean;
        g_meanvar[EMB + f] = 1.f / sqrtf(var + 1e-5f);
    }
}

// ---------------- fused: BN/update + scores + softmax(2 head-pairs) + keep + compact ----------------
__global__ void __launch_bounds__(512) k_A(int mode, const float* __restrict__ gam,
                    const float* __restrict__ bet,
                    const float* __restrict__ w4, float min_score) {
    int g = blockIdx.x, t = threadIdx.x;
    int w = t >> 5, lane = t & 31;
    __shared__ float sG[128], sBt[128], sMu[128], sRs[128];
    __shared__ float sW[4 * 128];
    __shared__ float sc[4][256];
    __shared__ float red[2][256];
    __shared__ int smask2[2][256];
    __shared__ int iarr[256];
    if (t < 128) {
        sG[t] = gam[t]; sBt[t] = bet[t];
        sMu[t] = g_meanvar[t]; sRs[t] = g_meanvar[EMB + t];
    }
    sW[t] = w4[t];
    __syncthreads();

    int f0 = lane * 4;
    float4 gg = *(float4*)&sG[f0], bb = *(float4*)&sBt[f0];
    float4 mm = *(float4*)&sMu[f0], rr = *(float4*)&sRs[f0];
    float4 w0v = *(float4*)&sW[0 * 128 + f0];
    float4 w1v = *(float4*)&sW[1 * 128 + f0];
    float4 w2v = *(float4*)&sW[2 * 128 + f0];
    float4 w3v = *(float4*)&sW[3 * 128 + f0];

    for (int i = 0; i < 16; i++) {
        int n = w * 16 + i;
        int gi = g * 256 + n;
        float4 v;
        if (mode == 0) {
            float4 b = *(const float4*)&g_buf[gi * EMB + f0];
            v.x = gg.x * (b.x - mm.x) * rr.x + bb.x;
            v.y = gg.y * (b.y - mm.y) * rr.y + bb.y;
            v.z = gg.z * (b.z - mm.z) * rr.z + bb.z;
            v.w = gg.w * (b.w - mm.w) * rr.w + bb.w;
        } else {
            float4 c = *(const float4*)&g_cur[gi * EMB + f0];
            unsigned mbp = g_mask[gi];
            float4 b = {0.f, 0.f, 0.f, 0.f};
            if (mbp) b = *(const float4*)&g_buf[gi * EMB + f0];
            float n0 = gg.x * (b.x - mm.x) * rr.x + bb.x;
            float n1 = gg.y * (b.y - mm.y) * rr.y + bb.y;
            float n2 = gg.z * (b.z - mm.z) * rr.z + bb.z;
            float n3 = gg.w * (b.w - mm.w) * rr.w + bb.w;
            v.x = 0.5f * c.x + 0.25f * n0;
            v.y = 0.5f * c.y + 0.25f * n1;
            v.z = 0.5f * c.z + 0.25f * n2;
            v.w = 0.5f * c.w + 0.25f * n3;
        }
        *(float4*)&g_cur[gi * EMB + f0] = v;
        float p0 = v.x * w0v.x + v.y * w0v.y + v.z * w0v.z + v.w * w0v.w;
        float p1 = v.x * w1v.x + v.y * w1v.y + v.z * w1v.z + v.w * w1v.w;
        float p2 = v.x * w2v.x + v.y * w2v.y + v.z * w2v.z + v.w * w2v.w;
        float p3 = v.x * w3v.x + v.y * w3v.y + v.z * w3v.z + v.w * w3v.w;
#pragma unroll
        for (int o = 16; o; o >>= 1) {
            p0 += __shfl_xor_sync(0xffffffffu, p0, o);
            p1 += __shfl_xor_sync(0xffffffffu, p1, o);
            p2 += __shfl_xor_sync(0xffffffffu, p2, o);
            p3 += __shfl_xor_sync(0xffffffffu, p3, o);
        }
        if (lane == 0) {
            sc[0][n] = p0; sc[1][n] = p1; sc[2][n] = p2; sc[3][n] = p3;
        }
    }
    __syncthreads();

    int g2 = t >> 8;
    int tn = t & 255;
    unsigned mbits = 0;
#pragma unroll
    for (int hh = 0; hh < 2; hh++) {
        int h = g2 * 2 + hh;
        float vv = sc[h][tn];
        red[g2][tn] = vv; __syncthreads();
        for (int o = 128; o > 0; o >>= 1) {
            if (tn < o) red[g2][tn] = fmaxf(red[g2][tn], red[g2][tn + o]);
            __syncthreads();
        }
        float m = red[g2][0]; __syncthreads();
        float e = expf(vv - m);
        red[g2][tn] = e; __syncthreads();
        for (int o = 128; o > 0; o >>= 1) {
            if (tn < o) red[g2][tn] += red[g2][tn + o];
            __syncthreads();
        }
        float s = red[g2][0]; __syncthreads();
        float sm = e / (s + 1e-16f);
        float smax = 1.0f / (s + 1e-16f);
        float thr = fminf(smax - 1e-7f, min_score);
        if (sm > thr) mbits |= (1u << hh);
        g_sm[h * NN + g * 256 + tn] = sm;
    }
    smask2[g2][tn] = (int)mbits;
    __syncthreads();

    int mb = 0, flag = 0;
    if (t < 256) {
        mb = smask2[0][t] | (smask2[1][t] << 2);
        g_mask[g * 256 + t] = (unsigned char)mb;
        flag = mb ? 1 : 0;
        iarr[t] = flag;
    }
    __syncthreads();
    for (int off = 1; off < 256; off <<= 1) {
        int xv = 0;
        if (t < 256 && t >= off) xv = iarr[t - off];
        __syncthreads();
        if (t < 256) iarr[t] += xv;
        __syncthreads();
    }
    if (t < 256 && flag) g_klist[g * 256 + iarr[t] - 1] = t | (mb << 8);
    if (t == 255) g_kcnt[g] = iarr[255];
}

// ---------------- block head conv on kept nodes + fused BN partials ----------------
__global__ void k_head(const float* __restrict__ wrel, const float* __restrict__ wroot,
                       const float* __restrict__ bias) {
    int g = blockIdx.x, t = threadIdx.x;
    int cnt = g_kcnt[g];
    int h = t >> 5, j = t & 31;
    __shared__ float sCur[128];
    __shared__ float sAgg[NHD][128];
    float s_acc = 0.f, ss_acc = 0.f;
    for (int kk = 0; kk < cnt; kk++) {
        int pk = g_klist[g * 256 + kk];
        int i = g * 256 + (pk & 255);
        unsigned mb = (pk >> 8) & 15;
        sCur[t] = g_cur[i * EMB + t];
        int beg = g_rp[i], end = g_rp[i + 1];
#pragma unroll
        for (int hh = 0; hh < NHD; hh++) {
            if (!((mb >> hh) & 1)) continue;
            float m = -3.4e38f;
            bool any = false;
            for (int e = beg; e < end; e++) {
                int sidx = g_csrc[e];
                if ((g_mask[sidx] >> hh) & 1) {
                    m = fmaxf(m, g_cur[sidx * EMB + t] * g_sm[hh * NN + sidx]);
                    any = true;
                }
            }
            sAgg[hh][t] = any ? m : 0.f;
        }
        __syncthreads();
        float v = 0.f;
        if ((mb >> h) & 1) {
            float smv = g_sm[h * NN + i];
            float accv = bias[h * OUTD + j];
            const float* wr = &wrel[(h * OUTD + j) * EMB];
            const float* wo = &wroot[(h * OUTD + j) * EMB];
#pragma unroll 16
            for (int k = 0; k < EMB; k++)
                accv += wr[k] * sAgg[h][k] + wo[k] * (sCur[k] * smv);
            v = lrelu(accv);
        }
        g_buf[i * EMB + t] = v;
        s_acc += v; ss_acc += v * v;
        __syncthreads();
    }
    g_part[g * EMB + t] = s_acc;
    g_part2[g * EMB + t] = ss_acc;
}

// ---------------- fused classifier ----------------
__global__ void k_cls(const float* __restrict__ gW1, const float* __restrict__ gb1,
                      const float* __restrict__ gW2, const float* __restrict__ gb2,
                      const float* __restrict__ fW1, const float* __restrict__ fb1,
                      const float* __restrict__ fW2, const float* __restrict__ fb2,
                      float* __restrict__ out) {
    int g = blockIdx.x, t = threadIdx.x;
    __shared__ float gate_s[NHD][256];
    __shared__ float red[128];
    __shared__ float sCur[128];
    __shared__ float sPool[128];
    __shared__ float sLog[NHD];
    for (int idx = t; idx < NHD * 256; idx += 128)
        ((float*)gate_s)[idx] = NEG_INF;
    int cnt = g_kcnt[g];
    __syncthreads();

    for (int kk = 0; kk < cnt; kk++) {
        int pk = g_klist[g * 256 + kk];
        int n = pk & 255;
        unsigned mb = (pk >> 8) & 15;
        int i = g * 256 + n;
        sCur[t] = g_cur[i * EMB + t];
        __syncthreads();
        for (int c = 0; c < NHD; c++) {
            if (!((mb >> c) & 1)) continue;
            float smv = g_sm[c * NN + i];
            float accv = gb1[c * EMB + t];
            const float* wp = &gW1[(c * EMB + t) * EMB];
#pragma unroll 16
            for (int k = 0; k < EMB; k++) accv += wp[k] * (sCur[k] * smv);
            accv = lrelu(accv);
            red[t] = accv * gW2[c * EMB + t];
            __syncthreads();
            for (int o = 64; o > 0; o >>= 1) {
                if (t < o) red[t] += red[t + o];
                __syncthreads();
            }
            if (t == 0) gate_s[c][n] = red[0] + gb2[c];
            __syncthreads();
        }
        __syncthreads();
    }

    for (int c = 0; c < NHD; c++) {
        red[t] = fmaxf(gate_s[c][t], gate_s[c][t + 128]);
        __syncthreads();
        for (int o = 64; o > 0; o >>= 1) {
            if (t < o) red[t] = fmaxf(red[t], red[t + o]);
            __syncthreads();
        }
        float m = red[0]; __syncthreads();
        float e0 = expf(gate_s[c][t] - m);
        float e1 = expf(gate_s[c][t + 128] - m);
        red[t] = e0 + e1;
        __syncthreads();
        for (int o = 64; o > 0; o >>= 1) {
            if (t < o) red[t] += red[t + o];
            __syncthreads();
        }
        float s = red[0] + 1e-16f; __syncthreads();

        float pool = 0.f;
        for (int kk = 0; kk < cnt; kk++) {
            int pk = g_klist[g * 256 + kk];
            int n = pk & 255;
            unsigned mb = (pk >> 8) & 15;
            if (!((mb >> c) & 1)) continue;
            int i = g * 256 + n;
            float a = expf(gate_s[c][n] - m) / s;
            pool += a * g_sm[c * NN + i] * g_cur[i * EMB + t];
        }
        sPool[t] = pool;
        __syncthreads();
        float accv = fb1[c * EMB + t];
        const float* wp = &fW1[(c * EMB + t) * EMB];
#pragma unroll 16
        for (int k = 0; k < EMB; k++) accv += wp[k] * sPool[k];
        accv = lrelu(accv);
        red[t] = accv * fW2[c * EMB + t];
        __syncthreads();
        for (int o = 64; o > 0; o >>= 1) {
            if (t < o) red[t] += red[t + o];
            __syncthreads();
        }
        if (t == 0) sLog[c] = red[0] + fb2[c];
        __syncthreads();
    }

    if (t < NHD) {
        float m = fmaxf(fmaxf(sLog[0], sLog[1]), fmaxf(sLog[2], sLog[3]));
        float s = expf(sLog[0] - m) + expf(sLog[1] - m) + expf(sLog[2] - m) + expf(sLog[3] - m);
        out[g * NHD + t] = sLog[t] - m - logf(s);
    }
}

// ---------------- launch ----------------
extern "C" void kernel_launch(void* const* d_in, const int* in_sizes, int n_in,
                              void* d_out, int out_size) {
    const float* x       = (const float*)d_in[0];
    const int*   ei      = (const int*)d_in[1];
    const int*   src     = ei;
    const int*   dst     = ei + EE;
    const float* Wrel0   = (const float*)d_in[3];
    const float* Wroot0  = (const float*)d_in[4];
    const float* b0      = (const float*)d_in[5];
    const float* bn0g    = (const float*)d_in[6];
    const float* bn0b    = (const float*)d_in[7];
    const float* blk_pw  = (const float*)d_in[8];
    const float* blk_Wr  = (const float*)d_in[9];
    const float* blk_Wo  = (const float*)d_in[10];
    const float* blk_bb  = (const float*)d_in[11];
    const float* blk_bng = (const float*)d_in[12];
    const float* blk_bnb = (const float*)d_in[13];
    const float* cls_pw  = (const float*)d_in[14];
    const float* gW1     = (const float*)d_in[15];
    const float* gb1     = (const float*)d_in[16];
    const float* gW2     = (const float*)d_in[17];
    const float* gb2     = (const float*)d_in[18];
    const float* fW1     = (const float*)d_in[19];
    const float* fb1     = (const float*)d_in[20];
    const float* fW2     = (const float*)d_in[21];
    const float* fb2     = (const float*)d_in[22];
    float* out = (float*)d_out;

    cudaFuncSetAttribute(k_convM, cudaFuncAttributeMaxDynamicSharedMemorySize, DSMEM);

    void* degp = 0;
    cudaGetSymbolAddress(&degp, g_deg);

    // CSR by dst
    cudaMemsetAsync(degp, 0, NN * sizeof(int), 0);
    k_hist<<<EE / 256, 256>>>(dst);
    k_scan1<<<256, 256>>>();
    k_scan2<<<1, 256>>>();
    k_scan3<<<256, 256>>>();
    k_scatter<<<EE / 256, 256>>>(src, dst);

    // conv0 (mma.sync tf32x3, fused stats) -> statsR -> A0
    k_agg0<<<NN / 8, 256>>>(x);
    k_convM<<<NN / 64, 256, DSMEM>>>(x, Wrel0, Wroot0, b0);
    k_statsR<<<EMB, 256>>>(NN / 64);
    k_A<<<BBG, 512>>>(0, bn0g, bn0b, blk_pw + 0 * NHD * EMB, 0.7f);

    // block 0
    k_head<<<BBG, 128>>>(blk_Wr, blk_Wo, blk_bb);
    k_statsR<<<EMB, 256>>>(BBG);
    k_A<<<BBG, 512>>>(1, blk_bng, blk_bnb, blk_pw + 1 * NHD * EMB, 0.7f);

    // block 1
    k_head<<<BBG, 128>>>(blk_Wr + NHD * OUTD * EMB, blk_Wo + NHD * OUTD * EMB, blk_bb + NHD * OUTD);
    k_statsR<<<EMB, 256>>>(BBG);
    k_A<<<BBG, 512>>>(1, blk_bng + EMB, blk_bnb + EMB, cls_pw, 0.8f);

    // classifier heads
    k_cls<<<BBG, 128>>>(gW1, gb1, gW2, gb2, fW1, fb1, fW2, fb2, out);
}

// round 16
// speedup vs baseline: 1.5594x; 1.0128x over previous
#include <cuda_runtime.h>
#include <cstdint>

#define NN 65536
#define EE 524288
#define BBG 256
#define FEAT 64
#define EMB 128
#define NHD 4
#define OUTD 32
#define NEG_INF __int_as_float(0xff800000)

// ---------------- scratch ----------------
__device__ float g_aggf[NN * FEAT];
__device__ float g_buf[NN * EMB];
__device__ float g_cur[NN * EMB];
__device__ float g_sm[NHD * NN];
__device__ unsigned char g_mask[NN];
__device__ float g_part[1024 * EMB];
__device__ float g_part2[1024 * EMB];
__device__ float g_meanvar[2 * EMB];
__device__ int g_klist[BBG * 256];
__device__ int g_kcnt[BBG];
__device__ int g_deg[NN];
__device__ int g_rp[NN + 1];
__device__ int g_cursor[NN];
__device__ int g_csrc[EE];
__device__ int g_bsum[256];
__device__ unsigned g_bar;

__device__ __forceinline__ float lrelu(float v) { return v > 0.f ? v : 0.01f * v; }

// ---------------- CSR build ----------------
__global__ void k_hist(const int* __restrict__ dst) {
    int e = blockIdx.x * blockDim.x + threadIdx.x;
    if (e < EE) atomicAdd(&g_deg[dst[e]], 1);
}
__global__ void k_scan1() {
    int b = blockIdx.x, t = threadIdx.x;
    if (b == 0 && t == 0) g_bar = 0;          // reset grid-barrier counter for mega
    int v = g_deg[b * 256 + t];
    __shared__ int a[256];
    a[t] = v; __syncthreads();
    for (int off = 1; off < 256; off <<= 1) {
        int x = (t >= off) ? a[t - off] : 0;
        __syncthreads(); a[t] += x; __syncthreads();
    }
    g_rp[b * 256 + t] = a[t] - v;
    if (t == 255) g_bsum[b] = a[t];
}
// scan3 with scan2 folded in: each block redundantly scans the 256 block sums
__global__ void k_scan3() {
    int b = blockIdx.x, t = threadIdx.x;
    __shared__ int a[256];
    a[t] = g_bsum[t];
    __syncthreads();
    for (int off = 1; off < 256; off <<= 1) {
        int x = (t >= off) ? a[t - off] : 0;
        __syncthreads(); a[t] += x; __syncthreads();
    }
    int boff = (b > 0) ? a[b - 1] : 0;
    int i = b * 256 + t;
    int r = g_rp[i] + boff;
    g_rp[i] = r;
    g_cursor[i] = r;
    if (i == 0) g_rp[NN] = EE;
}
__global__ void k_scatter(const int* __restrict__ src, const int* __restrict__ dst) {
    int e = blockIdx.x * blockDim.x + threadIdx.x;
    if (e < EE) {
        int p = atomicAdd(&g_cursor[dst[e]], 1);
        g_csrc[p] = src[e];
    }
}

// ---------------- conv0 max aggregation (warp per node, 2-edge ILP) ----------------
__global__ void k_agg0(const float* __restrict__ x) {
    int wi = (blockIdx.x * blockDim.x + threadIdx.x) >> 5;
    if (wi >= NN) return;
    int lane = threadIdx.x & 31;
    int beg = g_rp[wi], end = g_rp[wi + 1];
    float m0 = -3.4e38f, m1 = -3.4e38f;
    float n0 = -3.4e38f, n1 = -3.4e38f;
    int e = beg;
    for (; e + 1 < end; e += 2) {
        int s0 = g_csrc[e], s1 = g_csrc[e + 1];
        m0 = fmaxf(m0, x[s0 * FEAT + lane]);
        m1 = fmaxf(m1, x[s0 * FEAT + 32 + lane]);
        n0 = fmaxf(n0, x[s1 * FEAT + lane]);
        n1 = fmaxf(n1, x[s1 * FEAT + 32 + lane]);
    }
    if (e < end) {
        int s0 = g_csrc[e];
        m0 = fmaxf(m0, x[s0 * FEAT + lane]);
        m1 = fmaxf(m1, x[s0 * FEAT + 32 + lane]);
    }
    m0 = fmaxf(m0, n0);
    m1 = fmaxf(m1, n1);
    if (beg == end) { m0 = 0.f; m1 = 0.f; }
    g_aggf[wi * FEAT + lane] = m0;
    g_aggf[wi * FEAT + 32 + lane] = m1;
}

// ---------------- conv0 via mma.sync tf32x3 (R10-proven) ----------------
__device__ __forceinline__ uint32_t f2tf(float v) {
    uint32_t r;
    asm("cvt.rna.tf32.f32 %0, %1;" : "=r"(r) : "f"(v));
    return r;
}
#define MMA_TF32(c, a0, a1, a2, a3, b0, b1) \
    asm volatile("mma.sync.aligned.m16n8k8.row.col.f32.tf32.tf32.f32 " \
                 "{%0,%1,%2,%3}, {%4,%5,%6,%7}, {%8,%9}, {%0,%1,%2,%3};" \
                 : "+f"((c)[0]), "+f"((c)[1]), "+f"((c)[2]), "+f"((c)[3]) \
                 : "r"(a0), "r"(a1), "r"(a2), "r"(a3), "r"(b0), "r"(b1))

#define PITCH 132
#define DSMEM ((64 * PITCH + 128 * PITCH) * 4)
__global__ void __launch_bounds__(256) k_convM(const float* __restrict__ x,
                                               const float* __restrict__ wrel,
                                               const float* __restrict__ wroot,
                                               const float* __restrict__ b0) {
    extern __shared__ float smf[];
    float* sIn = smf;
    float* sW = smf + 64 * PITCH;
    __shared__ float2 sStat[8][32];
    int tx = threadIdx.x;
    int w = tx >> 5, lane = tx & 31;
    int gid = lane >> 2, tig = lane & 3;
    int nbase = blockIdx.x * 64;

#pragma unroll
    for (int it = 0; it < 8; it++) {
        int c = it * 256 + tx;
        int row = c >> 5, q = c & 31;
        float4 v = (q < 16) ? *(const float4*)&g_aggf[(nbase + row) * 64 + q * 4]
                            : *(const float4*)&x[(nbase + row) * 64 + (q - 16) * 4];
        *(float4*)&sIn[row * PITCH + q * 4] = v;
    }
#pragma unroll
    for (int it = 0; it < 16; it++) {
        int c = it * 256 + tx;
        int row = c >> 5, q = c & 31;
        float4 v = (q < 16) ? *(const float4*)&wrel[row * 64 + q * 4]
                            : *(const float4*)&wroot[row * 64 + (q - 16) * 4];
        *(float4*)&sW[row * PITCH + q * 4] = v;
    }
    __syncthreads();

    int mrow0 = (w & 1) * 32;
    int ocol0 = (w >> 1) * 32;

    float acc[2][4][4];
#pragma unroll
    for (int mt = 0; mt < 2; mt++)
#pragma unroll
        for (int nt = 0; nt < 4; nt++)
#pragma unroll
            for (int r = 0; r < 4; r++) acc[mt][nt][r] = 0.f;

    for (int kb = 0; kb < 128; kb += 8) {
        uint32_t ahi[2][4], alo[2][4], bhi[4][2], blo[4][2];
#pragma unroll
        for (int mt = 0; mt < 2; mt++) {
            int rb = mrow0 + mt * 16;
            float v0 = sIn[(rb + gid) * PITCH + kb + tig];
            float v1 = sIn[(rb + gid + 8) * PITCH + kb + tig];
            float v2 = sIn[(rb + gid) * PITCH + kb + tig + 4];
            float v3 = sIn[(rb + gid + 8) * PITCH + kb + tig + 4];
            ahi[mt][0] = f2tf(v0); alo[mt][0] = f2tf(v0 - __uint_as_float(ahi[mt][0]));
            ahi[mt][1] = f2tf(v1); alo[mt][1] = f2tf(v1 - __uint_as_float(ahi[mt][1]));
            ahi[mt][2] = f2tf(v2); alo[mt][2] = f2tf(v2 - __uint_as_float(ahi[mt][2]));
            ahi[mt][3] = f2tf(v3); alo[mt][3] = f2tf(v3 - __uint_as_float(ahi[mt][3]));
        }
#pragma unroll
        for (int nt = 0; nt < 4; nt++) {
            int n = ocol0 + nt * 8 + gid;
            float u0 = sW[n * PITCH + kb + tig];
            float u1 = sW[n * PITCH + kb + tig + 4];
            bhi[nt][0] = f2tf(u0); blo[nt][0] = f2tf(u0 - __uint_as_float(bhi[nt][0]));
            bhi[nt][1] = f2tf(u1); blo[nt][1] = f2tf(u1 - __uint_as_float(bhi[nt][1]));
        }
#pragma unroll
        for (int mt = 0; mt < 2; mt++)
#pragma unroll
            for (int nt = 0; nt < 4; nt++) {
                MMA_TF32(acc[mt][nt], ahi[mt][0], ahi[mt][1], ahi[mt][2], ahi[mt][3],
                         bhi[nt][0], bhi[nt][1]);
                MMA_TF32(acc[mt][nt], ahi[mt][0], ahi[mt][1], ahi[mt][2], ahi[mt][3],
                         blo[nt][0], blo[nt][1]);
                MMA_TF32(acc[mt][nt], alo[mt][0], alo[mt][1], alo[mt][2], alo[mt][3],
                         bhi[nt][0], bhi[nt][1]);
            }
    }

    float s0[4] = {0, 0, 0, 0}, s1[4] = {0, 0, 0, 0};
    float q0[4] = {0, 0, 0, 0}, q1[4] = {0, 0, 0, 0};
#pragma unroll
    for (int nt = 0; nt < 4; nt++) {
        int out0 = ocol0 + nt * 8 + 2 * tig;
        float bv0 = __ldg(&b0[out0]);
        float bv1 = __ldg(&b0[out0 + 1]);
#pragma unroll
        for (int mt = 0; mt < 2; mt++) {
            int node = nbase + mrow0 + mt * 16 + gid;
            float v00 = lrelu(acc[mt][nt][0] + bv0);
            float v01 = lrelu(acc[mt][nt][1] + bv1);
            float v10 = lrelu(acc[mt][nt][2] + bv0);
            float v11 = lrelu(acc[mt][nt][3] + bv1);
            *(float2*)&g_buf[node * EMB + out0] = make_float2(v00, v01);
            *(float2*)&g_buf[(node + 8) * EMB + out0] = make_float2(v10, v11);
            s0[nt] += v00 + v10; q0[nt] += v00 * v00 + v10 * v10;
            s1[nt] += v01 + v11; q1[nt] += v01 * v01 + v11 * v11;
        }
    }
#pragma unroll
    for (int o = 4; o <= 16; o <<= 1) {
#pragma unroll
        for (int nt = 0; nt < 4; nt++) {
            s0[nt] += __shfl_xor_sync(0xffffffffu, s0[nt], o);
            s1[nt] += __shfl_xor_sync(0xffffffffu, s1[nt], o);
            q0[nt] += __shfl_xor_sync(0xffffffffu, q0[nt], o);
            q1[nt] += __shfl_xor_sync(0xffffffffu, q1[nt], o);
        }
    }
    if (lane < 4) {
#pragma unroll
        for (int nt = 0; nt < 4; nt++) {
            sStat[w][nt * 8 + 2 * lane] = make_float2(s0[nt], q0[nt]);
            sStat[w][nt * 8 + 2 * lane + 1] = make_float2(s1[nt], q1[nt]);
        }
    }
    __syncthreads();
    if (tx < 128) {
        int oq = tx >> 5, idx = tx & 31;
        float2 p1 = sStat[2 * oq][idx];
        float2 p2 = sStat[2 * oq + 1][idx];
        g_part[blockIdx.x * EMB + tx] = p1.x + p2.x;
        g_part2[blockIdx.x * EMB + tx] = p1.y + p2.y;
    }
}

// ---------------- software grid barrier (all 256 blocks resident by construction) ----------------
__device__ __forceinline__ void gbar(unsigned phase) {
    __syncthreads();
    if (threadIdx.x == 0) {
        __threadfence();
        atomicAdd(&g_bar, 1u);
        unsigned target = 256u * phase;
        while (atomicAdd(&g_bar, 0u) < target) { }
    }
    __syncthreads();
    __threadfence();
}

// ---------------- MEGA tail: [stats -> A -> head] x2 -> stats -> A -> cls, one launch ----------------
__global__ void __launch_bounds__(512, 2) k_mega(
    const float* __restrict__ bn0g, const float* __restrict__ bn0b,
    const float* __restrict__ blk_pw,
    const float* __restrict__ blk_Wr, const float* __restrict__ blk_Wo,
    const float* __restrict__ blk_bb,
    const float* __restrict__ blk_bng, const float* __restrict__ blk_bnb,
    const float* __restrict__ cls_pw,
    const float* __restrict__ gW1, const float* __restrict__ gb1,
    const float* __restrict__ gW2, const float* __restrict__ gb2,
    const float* __restrict__ fW1, const float* __restrict__ fb1,
    const float* __restrict__ fW2, const float* __restrict__ fb2,
    float* __restrict__ out)
{
    int g = blockIdx.x, t = threadIdx.x;
    int w = t >> 5, lane = t & 31;

    __shared__ float shA[512], shB[512];
    __shared__ float sG[128], sBt[128], sMu[128], sRs[128];
    __shared__ float sWsc[512];
    __shared__ float sc4[4][256];
    __shared__ float redA[2][256];
    __shared__ int smask2[2][256];
    __shared__ int iarr[256];
    __shared__ float sCur[128];
    __shared__ float sAgg[4][128];
    __shared__ float gate_s[4][256];
    __shared__ float redC[128];
    __shared__ float sPool[128];
    __shared__ float sLog[4];

    unsigned barph = 0;

    for (int r = 0; r < 3; r++) {
        // ======== stats phase: blocks 0..127 reduce g_part -> g_meanvar ========
        {
            int P = (r == 0) ? (NN / 64) : 256;
            if (g < 128) {
                float s = 0.f, ss = 0.f;
                for (int p = t; p < P; p += 512) {
                    s += g_part[p * EMB + g];
                    ss += g_part2[p * EMB + g];
                }
                shA[t] = s; shB[t] = ss;
                __syncthreads();
                for (int o = 256; o > 0; o >>= 1) {
                    if (t < o) { shA[t] += shA[t + o]; shB[t] += shB[t + o]; }
                    __syncthreads();
                }
                if (t == 0) {
                    float mean = shA[0] * (1.f / NN);
                    float var = shB[0] * (1.f / NN) - mean * mean;
                    g_meanvar[g] = mean;
                    g_meanvar[EMB + g] = 1.f / sqrtf(var + 1e-5f);
                }
            }
        }
        gbar(++barph);

        // ======== A phase: BN/update + scores + softmax + keep + compact ========
        {
            int mode = (r == 0) ? 0 : 1;
            const float* gam = (r == 0) ? bn0g : (r == 1 ? blk_bng : blk_bng + EMB);
            const float* bet = (r == 0) ? bn0b : (r == 1 ? blk_bnb : blk_bnb + EMB);
            const float* w4  = (r == 0) ? blk_pw : (r == 1 ? blk_pw + NHD * EMB : cls_pw);
            float min_score = (r == 2) ? 0.8f : 0.7f;

            if (t < 128) {
                sG[t] = gam[t]; sBt[t] = bet[t];
                sMu[t] = g_meanvar[t]; sRs[t] = g_meanvar[EMB + t];
            }
            sWsc[t] = w4[t];
            __syncthreads();

            int f0 = lane * 4;
            float4 gg = *(float4*)&sG[f0], bb = *(float4*)&sBt[f0];
            float4 mm = *(float4*)&sMu[f0], rr = *(float4*)&sRs[f0];
            float4 w0v = *(float4*)&sWsc[0 * 128 + f0];
            float4 w1v = *(float4*)&sWsc[1 * 128 + f0];
            float4 w2v = *(float4*)&sWsc[2 * 128 + f0];
            float4 w3v = *(float4*)&sWsc[3 * 128 + f0];

            for (int i = 0; i < 16; i++) {
                int n = w * 16 + i;
                int gi = g * 256 + n;
                float4 v;
                if (mode == 0) {
                    float4 b = *(const float4*)&g_buf[gi * EMB + f0];
                    v.x = gg.x * (b.x - mm.x) * rr.x + bb.x;
                    v.y = gg.y * (b.y - mm.y) * rr.y + bb.y;
                    v.z = gg.z * (b.z - mm.z) * rr.z + bb.z;
                    v.w = gg.w * (b.w - mm.w) * rr.w + bb.w;
                } else {
                    float4 c = *(const float4*)&g_cur[gi * EMB + f0];
                    unsigned mbp = g_mask[gi];
                    float4 b = {0.f, 0.f, 0.f, 0.f};
                    if (mbp) b = *(const float4*)&g_buf[gi * EMB + f0];
                    float n0 = gg.x * (b.x - mm.x) * rr.x + bb.x;
                    float n1 = gg.y * (b.y - mm.y) * rr.y + bb.y;
                    float n2 = gg.z * (b.z - mm.z) * rr.z + bb.z;
                    float n3 = gg.w * (b.w - mm.w) * rr.w + bb.w;
                    v.x = 0.5f * c.x + 0.25f * n0;
                    v.y = 0.5f * c.y + 0.25f * n1;
                    v.z = 0.5f * c.z + 0.25f * n2;
                    v.w = 0.5f * c.w + 0.25f * n3;
                }
                *(float4*)&g_cur[gi * EMB + f0] = v;
                float p0 = v.x * w0v.x + v.y * w0v.y + v.z * w0v.z + v.w * w0v.w;
                float p1 = v.x * w1v.x + v.y * w1v.y + v.z * w1v.z + v.w * w1v.w;
                float p2 = v.x * w2v.x + v.y * w2v.y + v.z * w2v.z + v.w * w2v.w;
                float p3 = v.x * w3v.x + v.y * w3v.y + v.z * w3v.z + v.w * w3v.w;
#pragma unroll
                for (int o = 16; o; o >>= 1) {
                    p0 += __shfl_xor_sync(0xffffffffu, p0, o);
                    p1 += __shfl_xor_sync(0xffffffffu, p1, o);
                    p2 += __shfl_xor_sync(0xffffffffu, p2, o);
                    p3 += __shfl_xor_sync(0xffffffffu, p3, o);
                }
                if (lane == 0) {
                    sc4[0][n] = p0; sc4[1][n] = p1; sc4[2][n] = p2; sc4[3][n] = p3;
                }
            }
            __syncthreads();

            int g2 = t >> 8;
            int tn = t & 255;
            unsigned mbits = 0;
#pragma unroll
            for (int hh = 0; hh < 2; hh++) {
                int h = g2 * 2 + hh;
                float vv = sc4[h][tn];
                redA[g2][tn] = vv; __syncthreads();
                for (int o = 128; o > 0; o >>= 1) {
                    if (tn < o) redA[g2][tn] = fmaxf(redA[g2][tn], redA[g2][tn + o]);
                    __syncthreads();
                }
                float m = redA[g2][0]; __syncthreads();
                float e = expf(vv - m);
                redA[g2][tn] = e; __syncthreads();
                for (int o = 128; o > 0; o >>= 1) {
                    if (tn < o) redA[g2][tn] += redA[g2][tn + o];
                    __syncthreads();
                }
                float s = redA[g2][0]; __syncthreads();
                float sm = e / (s + 1e-16f);
                float smax = 1.0f / (s + 1e-16f);
                float thr = fminf(smax - 1e-7f, min_score);
                if (sm > thr) mbits |= (1u << hh);
                g_sm[h * NN + g * 256 + tn] = sm;
            }
            smask2[g2][tn] = (int)mbits;
            __syncthreads();

            int mb = 0, flag = 0;
            if (t < 256) {
                mb = smask2[0][t] | (smask2[1][t] << 2);
                g_mask[g * 256 + t] = (unsigned char)mb;
                flag = mb ? 1 : 0;
                iarr[t] = flag;
            }
            __syncthreads();
            for (int off = 1; off < 256; off <<= 1) {
                int xv = 0;
                if (t < 256 && t >= off) xv = iarr[t - off];
                __syncthreads();
                if (t < 256) iarr[t] += xv;
                __syncthreads();
            }
            if (t < 256 && flag) g_klist[g * 256 + iarr[t] - 1] = t | (mb << 8);
            if (t == 255) g_kcnt[g] = iarr[255];
            __syncthreads();   // FIX: order klist/kcnt writes before same-block fall-through (r=2 -> cls)
        }

        if (r < 2) {
            gbar(++barph);

            // ======== head phase: GraphConv(max) at kept nodes, 4 heads in parallel ========
            {
                const float* wrel = blk_Wr + r * NHD * OUTD * EMB;
                const float* wroot = blk_Wo + r * NHD * OUTD * EMB;
                const float* bias = blk_bb + r * NHD * OUTD;
                int cnt = g_kcnt[g];
                int f = t & 127;
                int hd = t >> 7;
                float s_acc = 0.f, ss_acc = 0.f;
                for (int kk = 0; kk < cnt; kk++) {
                    int pk = g_klist[g * 256 + kk];
                    int i = g * 256 + (pk & 255);
                    unsigned mb = (pk >> 8) & 15;
                    if (t < 128) sCur[t] = g_cur[i * EMB + t];
                    if ((mb >> hd) & 1) {
                        int beg = g_rp[i], end = g_rp[i + 1];
                        float m = -3.4e38f;
                        bool any = false;
                        for (int e = beg; e < end; e++) {
                            int sidx = g_csrc[e];
                            if ((g_mask[sidx] >> hd) & 1) {
                                m = fmaxf(m, g_cur[sidx * EMB + f] * g_sm[hd * NN + sidx]);
                                any = true;
                            }
                        }
                        sAgg[hd][f] = any ? m : 0.f;
                    }
                    __syncthreads();
                    if (t < 128) {
                        int h = t >> 5, j = t & 31;
                        float v = 0.f;
                        if ((mb >> h) & 1) {
                            float smv = g_sm[h * NN + i];
                            const float* wr = &wrel[(h * OUTD + j) * EMB];
                            const float* wo = &wroot[(h * OUTD + j) * EMB];
                            float a0 = 0, a1 = 0, a2 = 0, a3 = 0;
#pragma unroll
                            for (int k = 0; k < EMB; k += 4) {
                                a0 += wr[k] * sAgg[h][k] + wo[k] * (sCur[k] * smv);
                                a1 += wr[k + 1] * sAgg[h][k + 1] + wo[k + 1] * (sCur[k + 1] * smv);
                                a2 += wr[k + 2] * sAgg[h][k + 2] + wo[k + 2] * (sCur[k + 2] * smv);
                                a3 += wr[k + 3] * sAgg[h][k + 3] + wo[k + 3] * (sCur[k + 3] * smv);
                            }
                            v = lrelu(bias[h * OUTD + j] + a0 + a1 + a2 + a3);
                        }
                        g_buf[i * EMB + t] = v;
                        s_acc += v; ss_acc += v * v;
                    }
                    __syncthreads();
                }
                if (t < 128) {
                    g_part[g * EMB + t] = s_acc;
                    g_part2[g * EMB + t] = ss_acc;
                }
            }
            gbar(++barph);
        }
    }

    // ======== cls phase (same-block data; ordering provided by trailing A-phase sync) ========
    {
        for (int idx = t; idx < NHD * 256; idx += 512)
            ((float*)gate_s)[idx] = NEG_INF;
        __syncthreads();
        int cnt = g_kcnt[g];

        for (int kk = 0; kk < cnt; kk++) {
            int pk = g_klist[g * 256 + kk];
            int n = pk & 255;
            unsigned mb = (pk >> 8) & 15;
            int i = g * 256 + n;
            if (t < 128) sCur[t] = g_cur[i * EMB + t];
            __syncthreads();
            for (int c = 0; c < NHD; c++) {
                if (!((mb >> c) & 1)) continue;
                if (t < 128) {
                    float smv = g_sm[c * NN + i];
                    const float* wp = &gW1[(c * EMB + t) * EMB];
                    float a0 = 0, a1 = 0, a2 = 0, a3 = 0;
#pragma unroll
                    for (int k = 0; k < EMB; k += 4) {
                        a0 += wp[k] * (sCur[k] * smv);
                        a1 += wp[k + 1] * (sCur[k + 1] * smv);
                        a2 += wp[k + 2] * (sCur[k + 2] * smv);
                        a3 += wp[k + 3] * (sCur[k + 3] * smv);
                    }
                    float accv = lrelu(gb1[c * EMB + t] + a0 + a1 + a2 + a3);
                    redC[t] = accv * gW2[c * EMB + t];
                }
                __syncthreads();
                for (int o = 64; o > 0; o >>= 1) {
                    if (t < o) redC[t] += redC[t + o];
                    __syncthreads();
                }
                if (t == 0) gate_s[c][n] = redC[0] + gb2[c];
                __syncthreads();
            }
        }

        for (int c = 0; c < NHD; c++) {
            if (t < 128) redC[t] = fmaxf(gate_s[c][t], gate_s[c][t + 128]);
            __syncthreads();
            for (int o = 64; o > 0; o >>= 1) {
                if (t < o) redC[t] = fmaxf(redC[t], redC[t + o]);
                __syncthreads();
            }
            float m = redC[0]; __syncthreads();
            if (t < 128) redC[t] = expf(gate_s[c][t] - m) + expf(gate_s[c][t + 128] - m);
            __syncthreads();
            for (int o = 64; o > 0; o >>= 1) {
                if (t < o) redC[t] += redC[t + o];
                __syncthreads();
            }
            float s = redC[0] + 1e-16f; __syncthreads();

            if (t < 128) {
                float pool = 0.f;
                for (int kk = 0; kk < cnt; kk++) {
                    int pk = g_klist[g * 256 + kk];
                    int n = pk & 255;
                    unsigned mb = (pk >> 8) & 15;
                    if (!((mb >> c) & 1)) continue;
                    int i = g * 256 + n;
                    float a = expf(gate_s[c][n] - m) / s;
                    pool += a * g_sm[c * NN + i] * g_cur[i * EMB + t];
                }
                sPool[t] = pool;
            }
            __syncthreads();
            if (t < 128) {
                const float* wp = &fW1[(c * EMB + t) * EMB];
                float a0 = 0, a1 = 0, a2 = 0, a3 = 0;
#pragma unroll
                for (int k = 0; k < EMB; k += 4) {
                    a0 += wp[k] * sPool[k];
                    a1 += wp[k + 1] * sPool[k + 1];
                    a2 += wp[k + 2] * sPool[k + 2];
                    a3 += wp[k + 3] * sPool[k + 3];
                }
                float accv = lrelu(fb1[c * EMB + t] + a0 + a1 + a2 + a3);
                redC[t] = accv * fW2[c * EMB + t];
            }
            __syncthreads();
            for (int o = 64; o > 0; o >>= 1) {
                if (t < o) redC[t] += redC[t + o];
                __syncthreads();
            }
            if (t == 0) sLog[c] = redC[0] + fb2[c];
            __syncthreads();
        }

        if (t < NHD) {
            float m = fmaxf(fmaxf(sLog[0], sLog[1]), fmaxf(sLog[2], sLog[3]));
            float s = expf(sLog[0] - m) + expf(sLog[1] - m) + expf(sLog[2] - m) + expf(sLog[3] - m);
            out[g * NHD + t] = sLog[t] - m - logf(s);
        }
    }
}

// ---------------- launch ----------------
extern "C" void kernel_launch(void* const* d_in, const int* in_sizes, int n_in,
                              void* d_out, int out_size) {
    const float* x       = (const float*)d_in[0];
    const int*   ei      = (const int*)d_in[1];
    const int*   src     = ei;
    const int*   dst     = ei + EE;
    const float* Wrel0   = (const float*)d_in[3];
    const float* Wroot0  = (const float*)d_in[4];
    const float* b0      = (const float*)d_in[5];
    const float* bn0g    = (const float*)d_in[6];
    const float* bn0b    = (const float*)d_in[7];
    const float* blk_pw  = (const float*)d_in[8];
    const float* blk_Wr  = (const float*)d_in[9];
    const float* blk_Wo  = (const float*)d_in[10];
    const float* blk_bb  = (const float*)d_in[11];
    const float* blk_bng = (const float*)d_in[12];
    const float* blk_bnb = (const float*)d_in[13];
    const float* cls_pw  = (const float*)d_in[14];
    const float* gW1     = (const float*)d_in[15];
    const float* gb1     = (const float*)d_in[16];
    const float* gW2     = (const float*)d_in[17];
    const float* gb2     = (const float*)d_in[18];
    const float* fW1     = (const float*)d_in[19];
    const float* fb1     = (const float*)d_in[20];
    const float* fW2     = (const float*)d_in[21];
    const float* fb2     = (const float*)d_in[22];
    float* out = (float*)d_out;

    cudaFuncSetAttribute(k_convM, cudaFuncAttributeMaxDynamicSharedMemorySize, DSMEM);

    void* degp = 0;
    cudaGetSymbolAddress(&degp, g_deg);

    // CSR by dst
    cudaMemsetAsync(degp, 0, NN * sizeof(int), 0);
    k_hist<<<EE / 256, 256>>>(dst);
    k_scan1<<<256, 256>>>();                  // also resets g_bar
    k_scan3<<<256, 256>>>();                  // scan2 folded in
    k_scatter<<<EE / 256, 256>>>(src, dst);

    // conv0 (mma.sync tf32x3, fused stats)
    k_agg0<<<NN / 8, 256>>>(x);
    k_convM<<<NN / 64, 256, DSMEM>>>(x, Wrel0, Wroot0, b0);

    // fused tail: 9 launches -> 1
    k_mega<<<BBG, 512>>>(bn0g, bn0b, blk_pw, blk_Wr, blk_Wo, blk_bb,
                         blk_bng, blk_bnb, cls_pw,
                         gW1, gb1, gW2, gb2, fW1, fb1, fW2, fb2, out);
}